// round 6
// baseline (speedup 1.0000x reference)
#include <cuda_runtime.h>
#include <cuda_fp16.h>
#include <stdint.h>

#define B_ 4
#define C_ 256
#define N_ 4096

// ---------------- device scratch (swizzled tile layouts, attn-ready) --------
__device__ __align__(256) __half g_qt [(size_t)B_ * 64 * 4096]; // 8KB q-tiles [r][qh32|ql32] sw128
__device__ __align__(256) __half g_kt [(size_t)B_ * 64 * 4096]; // 8KB k-tiles
__device__ __align__(256) __half g_vt [(size_t)B_ * 64 * 16384];// 32KB V^T tiles [c][n] sw128

// ---------------- asm helpers ----------------
__device__ __forceinline__ uint32_t smem_u32(const void* p) {
    uint32_t a;
    asm("{ .reg .u64 t; cvta.to.shared.u64 t, %1; cvt.u32.u64 %0, t; }" : "=r"(a) : "l"(p));
    return a;
}
__device__ __forceinline__ void ldsm4(uint32_t* r, uint32_t a) {
    asm volatile("ldmatrix.sync.aligned.m8n8.x4.shared.b16 {%0,%1,%2,%3}, [%4];"
        : "=r"(r[0]), "=r"(r[1]), "=r"(r[2]), "=r"(r[3]) : "r"(a));
}
__device__ __forceinline__ void mma16816(float* c, const uint32_t* a, const uint32_t* b) {
    asm volatile("mma.sync.aligned.m16n8k16.row.col.f32.f16.f16.f32 "
        "{%0,%1,%2,%3}, {%4,%5,%6,%7}, {%8,%9}, {%0,%1,%2,%3};"
        : "+f"(c[0]), "+f"(c[1]), "+f"(c[2]), "+f"(c[3])
        : "r"(a[0]), "r"(a[1]), "r"(a[2]), "r"(a[3]), "r"(b[0]), "r"(b[1]));
}
__device__ __forceinline__ uint32_t pk(float lo, float hi) {
    uint32_t r;
    asm("cvt.rn.f16x2.f32 %0, %1, %2;" : "=r"(r) : "f"(hi), "f"(lo));
    return r;
}
#define MBAR_INIT(m, c) \
    asm volatile("mbarrier.init.shared.b64 [%0], %1;" :: "r"((uint32_t)(m)), "r"((uint32_t)(c)) : "memory")
#define MBAR_EXPECT_TX(m, b) \
    asm volatile("mbarrier.arrive.expect_tx.shared.b64 _, [%0], %1;" :: "r"((uint32_t)(m)), "r"((uint32_t)(b)) : "memory")
#define MBAR_WAIT(m, ph) do { \
    uint32_t _m = (uint32_t)(m), _p = (uint32_t)(ph), _d; \
    asm volatile("{\n\t.reg .pred p;\n\t" \
        "mbarrier.try_wait.parity.acquire.cta.shared::cta.b64 p, [%1], %2;\n\tselp.b32 %0,1,0,p;\n\t}" \
        : "=r"(_d) : "r"(_m), "r"(_p) : "memory"); \
    if (!_d) { asm volatile("{\n\t.reg .pred P1;\n\tWL_%=:\n\t" \
        "mbarrier.try_wait.parity.acquire.cta.shared::cta.b64 P1, [%0], %1, 0x989680;\n\t" \
        "@P1 bra.uni WD_%=;\n\tbra.uni WL_%=;\n\tWD_%=:\n\t}" :: "r"(_m), "r"(_p) : "memory"); } \
} while (0)
__device__ __forceinline__ void bulk_g2s(uint32_t dst, const void* src, uint32_t bytes, uint32_t mbar) {
    asm volatile("cp.async.bulk.shared::cluster.global.mbarrier::complete_tx::bytes [%0], [%1], %2, [%3];"
        :: "r"(dst), "l"(__cvta_generic_to_global(src)), "r"(bytes), "r"(mbar) : "memory");
}

// ---------------------------------------------------------------------------
// Kernel 1: QKV projection (FFMA) writing DIRECTLY into swizzled tile layouts.
//   j0 in {0,128}  -> V rows -> g_vt ([c][n] fp16, sw128)
//   j0 == 256      -> Q (cols 0..31) / K (cols 32..63) hi/lo -> g_qt / g_kt
// ---------------------------------------------------------------------------
__global__ __launch_bounds__(256) void qkv_proj_kernel(
    const float* __restrict__ x, const float* __restrict__ wv,
    const float* __restrict__ wq, const float* __restrict__ wk)
{
    const int b = blockIdx.z, nb = blockIdx.x * 128, j0 = blockIdx.y * 128;
    const int tid = threadIdx.x, tyy = tid >> 4, txx = tid & 15;
    __shared__ float xs[16][128];
    __shared__ float ws[16][132];
    float acc[8][8];
#pragma unroll
    for (int i = 0; i < 8; i++)
#pragma unroll
        for (int j = 0; j < 8; j++) acc[i][j] = 0.f;
    const float* xb = x + (size_t)b * C_ * N_;

    for (int c0 = 0; c0 < C_; c0 += 16) {
#pragma unroll
        for (int w = 0; w < 2; w++) {
            int f4 = tid + w * 256, k = f4 >> 5, n4 = f4 & 31;
            *(float4*)(&xs[k][n4 * 4]) = *(const float4*)(xb + (size_t)(c0 + k) * N_ + nb + n4 * 4);
        }
#pragma unroll
        for (int it = 0; it < 8; it++) {
            int jl = (tid >> 4) + it * 16, k = tid & 15, j = j0 + jl, c = c0 + k;
            float v = 0.f;
            if (j < 256) v = wv[j * C_ + c];
            else if (j < 288) v = wq[(j - 256) * C_ + c];
            else if (j < 320) v = wk[(j - 288) * C_ + c];
            ws[k][jl] = v;
        }
        __syncthreads();
#pragma unroll
        for (int k = 0; k < 16; k++) {
            float a[8], bb[8];
            *(float4*)&a[0]  = *(const float4*)&xs[k][tyy * 4];
            *(float4*)&a[4]  = *(const float4*)&xs[k][64 + tyy * 4];
            *(float4*)&bb[0] = *(const float4*)&ws[k][txx * 4];
            *(float4*)&bb[4] = *(const float4*)&ws[k][64 + txx * 4];
#pragma unroll
            for (int i = 0; i < 8; i++)
#pragma unroll
                for (int j = 0; j < 8; j++) acc[i][j] = fmaf(a[i], bb[j], acc[i][j]);
        }
        __syncthreads();
    }

    if (j0 < 256) {
        // V^T: acc[i][j] = V[n][c]; write 4 consecutive n per c as one 8B chunk.
#pragma unroll
        for (int half = 0; half < 2; half++) {
            int n0 = nb + half * 64 + tyy * 4;      // 4 consecutive n
            int tkey = n0 >> 6, nl0 = n0 & 63;
            char* tb = (char*)(g_vt + ((size_t)(b * 64 + tkey)) * 16384);
            uint32_t sw = (uint32_t)(nl0 * 2);      // 8-aligned; swizzle bits constant over run
#pragma unroll
            for (int g = 0; g < 2; g++)
#pragma unroll
                for (int jj = 0; jj < 4; jj++) {
                    int c = j0 + g * 64 + txx * 4 + jj;
                    __half h[4];
                    h[0] = __float2half_rn(acc[half * 4 + 0][g * 4 + jj]);
                    h[1] = __float2half_rn(acc[half * 4 + 1][g * 4 + jj]);
                    h[2] = __float2half_rn(acc[half * 4 + 2][g * 4 + jj]);
                    h[3] = __float2half_rn(acc[half * 4 + 3][g * 4 + jj]);
                    *(uint2*)(tb + c * 128 + (sw ^ ((c & 7) << 4))) = *(uint2*)h;
                }
        }
    } else {
        const int q4 = txx * 4;
        const bool isQ = q4 < 32;
        const int qc = isQ ? q4 : q4 - 32;
        __half* base = isQ ? g_qt : g_kt;
#pragma unroll
        for (int i = 0; i < 8; i++) {
            int row = nb + ((i < 4) ? (tyy * 4 + i) : (64 + tyy * 4 + i - 4));
            int tq = row >> 6, r = row & 63;
            char* tb = (char*)(base + ((size_t)(b * 64 + tq)) * 4096);
            __half hi[4], lo[4];
#pragma unroll
            for (int jj = 0; jj < 4; jj++) {
                float a = acc[i][jj];
                __half h = __float2half_rn(a);
                hi[jj] = h;
                lo[jj] = __float2half_rn(a - __half2float(h));
            }
            *(uint2*)(tb + r * 128 + ((qc * 2)        ^ ((r & 7) << 4))) = *(uint2*)hi;
            *(uint2*)(tb + r * 128 + (((64 + qc * 2)) ^ ((r & 7) << 4))) = *(uint2*)lo;
        }
    }
}

// ---------------------------------------------------------------------------
// Kernel 2: HMMA flash attention, software-pipelined:
//   softmax(t) -> [ GEMM1(t+1) || GEMM2(t) ]  (independent chains)
// K loaded 2 tiles ahead, V 1 ahead; split barriers barK[2], barV[2].
// ---------------------------------------------------------------------------
#define OFF_RDT 0
#define OFF_Q   16384
#define OFF_K   24576      /* 2 x 8192 */
#define OFF_V   40960      /* 2 x 32768 */
#define OFF_BAR 106496     /* barK0 barK1 barV0 barV1 */
#define SMEM_SZ 106624

__device__ __forceinline__ void gemm1(float s[8][4], const uint32_t qf[2][2][4],
                                      uint32_t bK, int lane) {
#pragma unroll
    for (int i = 0; i < 8; i++)
#pragma unroll
        for (int j = 0; j < 4; j++) s[i][j] = 0.f;
#pragma unroll
    for (int kk = 0; kk < 2; kk++)
#pragma unroll
        for (int jp = 0; jp < 4; jp++) {
            int row = jp * 16 + (lane & 7) + ((lane & 16) ? 8 : 0);
            int colb = kk * 32 + ((lane & 8) ? 16 : 0);
            uint32_t bh[4], bl[4];
            ldsm4(bh, bK + row * 128 + (colb ^ ((row & 7) << 4)));
            ldsm4(bl, bK + row * 128 + ((colb + 64) ^ ((row & 7) << 4)));
            mma16816(s[jp*2],   qf[0][kk], bh);
            mma16816(s[jp*2+1], qf[0][kk], bh + 2);
            mma16816(s[jp*2],   qf[1][kk], bh);
            mma16816(s[jp*2+1], qf[1][kk], bh + 2);
            mma16816(s[jp*2],   qf[0][kk], bl);
            mma16816(s[jp*2+1], qf[0][kk], bl + 2);
        }
}

__global__ __launch_bounds__(256, 1) void attn_kernel(
    const float* __restrict__ x, const float* __restrict__ gamma,
    const float* __restrict__ beta, const float* __restrict__ mean,
    const float* __restrict__ var, float* __restrict__ out)
{
    extern __shared__ char smc[];
    float* rdt = (float*)(smc + OFF_RDT);
    const uint32_t sb = smem_u32(smc);
    const uint32_t barK0 = sb + OFF_BAR, barK1 = sb + OFF_BAR + 8;
    const uint32_t barV0 = sb + OFF_BAR + 16, barV1 = sb + OFF_BAR + 24;
    const int tid = threadIdx.x, w = tid >> 5, lane = tid & 31;
    const int wm = w & 3, wc = w >> 2;
    const int b = blockIdx.y, qt = blockIdx.x, qb = qt * 64;

    for (int i = tid; i < 4096; i += 256) {
        int dy = i >> 6, dx = i & 63;
        rdt[i] = 1.0f / (sqrtf((float)(dy * dy + dx * dx)) + 1.0f);
    }
    {
        const uint4* qsrc = (const uint4*)(g_qt + ((size_t)(b * 64 + qt)) * 4096);
        uint4* qdst = (uint4*)(smc + OFF_Q);
#pragma unroll
        for (int it = 0; it < 2; it++) qdst[tid + it * 256] = qsrc[tid + it * 256];
    }
    if (tid == 0) {
        MBAR_INIT(barK0, 1); MBAR_INIT(barK1, 1);
        MBAR_INIT(barV0, 1); MBAR_INIT(barV1, 1);
    }
    __syncthreads();

    // persistent Q A-frags
    uint32_t qf[2][2][4];
#pragma unroll
    for (int hl = 0; hl < 2; hl++)
#pragma unroll
        for (int kk = 0; kk < 2; kk++) {
            int row = wm * 16 + (lane & 7) + ((lane & 8) ? 8 : 0);
            int colb = hl * 64 + kk * 32 + ((lane & 16) ? 16 : 0);
            ldsm4(qf[hl][kk], sb + OFF_Q + row * 128 + (colb ^ ((row & 7) << 4)));
        }

    const __half* kt = g_kt + (size_t)b * 64 * 4096;
    const __half* vt = g_vt + (size_t)b * 64 * 16384;

    // prologue: K(0), V(0), K(1)
    if (tid == 0) {
        MBAR_EXPECT_TX(barK0, 8192);  bulk_g2s(sb + OFF_K, kt, 8192, barK0);
        MBAR_EXPECT_TX(barV0, 32768); bulk_g2s(sb + OFF_V, vt, 32768, barV0);
        MBAR_EXPECT_TX(barK1, 8192);  bulk_g2s(sb + OFF_K + 8192, kt + 4096, 8192, barK1);
    }

    float y[16][4];
#pragma unroll
    for (int i = 0; i < 16; i++)
#pragma unroll
        for (int j = 0; j < 4; j++) y[i][j] = 0.f;
    float mA = -1e30f, mB = -1e30f, lA = 0.f, lB = 0.f;
    const int rxA = wm * 16 + (lane >> 2), rxB = rxA + 8;
    const int c0 = 2 * (lane & 3);

    // S(0)
    float s[8][4];
    MBAR_WAIT(barK0, 0);
    gemm1(s, qf, sb + OFF_K, lane);
    __syncthreads();   // all warps done with K stage0 before K(2) overwrites it

    for (int t = 0; t < 64; t++) {
        if (tid == 0) {
            if (t + 2 < 64) {
                uint32_t bk = (t & 1) ? barK1 : barK0;
                MBAR_EXPECT_TX(bk, 8192);
                bulk_g2s(sb + OFF_K + (t & 1) * 8192, kt + (size_t)(t + 2) * 4096, 8192, bk);
            }
            if (t + 1 < 64) {
                uint32_t bv = ((t + 1) & 1) ? barV1 : barV0;
                MBAR_EXPECT_TX(bv, 32768);
                bulk_g2s(sb + OFF_V + ((t + 1) & 1) * 32768, vt + (size_t)(t + 1) * 16384, 32768, bv);
            }
        }

        // ---- softmax(t): consume s -> pf
        const float* rdtp = rdt + ((qt > t) ? (qt - t) : (t - qt)) * 64;
        float tmA = -1e30f, tmB = -1e30f;
#pragma unroll
        for (int j = 0; j < 8; j++) {
            int c = j * 8 + c0;
            int d0 = rxA - c;     d0 = d0 < 0 ? -d0 : d0;
            int d1 = rxA - c - 1; d1 = d1 < 0 ? -d1 : d1;
            int d2 = rxB - c;     d2 = d2 < 0 ? -d2 : d2;
            int d3 = rxB - c - 1; d3 = d3 < 0 ? -d3 : d3;
            s[j][0] *= rdtp[d0];
            s[j][1] *= rdtp[d1];
            s[j][2] *= rdtp[d2];
            s[j][3] *= rdtp[d3];
            tmA = fmaxf(tmA, fmaxf(s[j][0], s[j][1]));
            tmB = fmaxf(tmB, fmaxf(s[j][2], s[j][3]));
        }
        tmA = fmaxf(tmA, __shfl_xor_sync(0xffffffffu, tmA, 1));
        tmA = fmaxf(tmA, __shfl_xor_sync(0xffffffffu, tmA, 2));
        tmB = fmaxf(tmB, __shfl_xor_sync(0xffffffffu, tmB, 1));
        tmB = fmaxf(tmB, __shfl_xor_sync(0xffffffffu, tmB, 2));
        float mnA = fmaxf(mA, tmA), mnB = fmaxf(mB, tmB);
        float scA = __expf(mA - mnA), scB = __expf(mB - mnB);
        mA = mnA; mB = mnB;
        if (!__all_sync(0xffffffffu, (scA == 1.f) && (scB == 1.f))) {
            lA *= scA; lB *= scB;
#pragma unroll
            for (int nt = 0; nt < 16; nt++) {
                y[nt][0] *= scA; y[nt][1] *= scA;
                y[nt][2] *= scB; y[nt][3] *= scB;
            }
        }
        float sumA = 0.f, sumB = 0.f;
        uint32_t pf[4][4];
#pragma unroll
        for (int j = 0; j < 8; j++) {
            float p0 = __expf(s[j][0] - mnA), p1 = __expf(s[j][1] - mnA);
            float p2 = __expf(s[j][2] - mnB), p3 = __expf(s[j][3] - mnB);
            sumA += p0 + p1; sumB += p2 + p3;
            int kk = j >> 1;
            if (!(j & 1)) { pf[kk][0] = pk(p0, p1); pf[kk][1] = pk(p2, p3); }
            else          { pf[kk][2] = pk(p0, p1); pf[kk][3] = pk(p2, p3); }
        }
        sumA += __shfl_xor_sync(0xffffffffu, sumA, 1);
        sumA += __shfl_xor_sync(0xffffffffu, sumA, 2);
        sumB += __shfl_xor_sync(0xffffffffu, sumB, 1);
        sumB += __shfl_xor_sync(0xffffffffu, sumB, 2);
        lA += sumA; lB += sumB;

        // ---- wait data, then two INDEPENDENT MMA streams in one block
        if (t + 1 < 64) MBAR_WAIT((((t + 1) & 1) ? barK1 : barK0), ((t + 1) >> 1) & 1);
        MBAR_WAIT(((t & 1) ? barV1 : barV0), (t >> 1) & 1);

        if (t + 1 < 64)
            gemm1(s, qf, sb + OFF_K + ((t + 1) & 1) * 8192, lane);   // S(t+1)

        const uint32_t bV = sb + OFF_V + (t & 1) * 32768;
#pragma unroll
        for (int kk = 0; kk < 4; kk++)
#pragma unroll
            for (int np = 0; np < 8; np++) {
                int row = wc * 128 + np * 16 + (lane & 7) + ((lane & 16) ? 8 : 0);
                int colb = kk * 32 + ((lane & 8) ? 16 : 0);
                uint32_t bv[4];
                ldsm4(bv, bV + row * 128 + (colb ^ ((row & 7) << 4)));
                mma16816(y[np*2],   pf[kk], bv);
                mma16816(y[np*2+1], pf[kk], bv + 2);
            }
        __syncthreads();   // stage reuse guard
    }

    // ---- epilogue: normalize, transpose via smem, BN + ReLU + residual
    float* Ys = (float*)smc;     // [64][257]
    float rA = 1.f / lA, rB = 1.f / lB;
#pragma unroll
    for (int nt = 0; nt < 16; nt++) {
        int c = wc * 128 + nt * 8 + c0;
        Ys[rxA * 257 + c]     = y[nt][0] * rA;
        Ys[rxA * 257 + c + 1] = y[nt][1] * rA;
        Ys[rxB * 257 + c]     = y[nt][2] * rB;
        Ys[rxB * 257 + c + 1] = y[nt][3] * rB;
    }
    __syncthreads();
    const int n = tid & 63, cg = tid >> 6;
    for (int it = 0; it < 64; it++) {
        int c = it * 4 + cg;
        float inv = gamma[c] * rsqrtf(var[c] + 1e-5f);
        float add = fmaf(-mean[c], inv, beta[c]);
        size_t idx = ((size_t)b * C_ + c) * N_ + qb + n;
        float yv = Ys[n * 257 + c];
        out[idx] = fmaxf(fmaf(yv, inv, add), 0.f) + x[idx];
    }
}

// ---------------------------------------------------------------------------
extern "C" void kernel_launch(void* const* d_in, const int* in_sizes, int n_in,
                              void* d_out, int out_size)
{
    (void)in_sizes; (void)n_in; (void)out_size;
    const float* x     = (const float*)d_in[0];
    const float* wv    = (const float*)d_in[1];
    const float* wq    = (const float*)d_in[2];
    const float* wk    = (const float*)d_in[3];
    const float* gamma = (const float*)d_in[4];
    const float* beta  = (const float*)d_in[5];
    const float* mean  = (const float*)d_in[6];
    const float* var   = (const float*)d_in[7];
    float* out = (float*)d_out;

    qkv_proj_kernel<<<dim3(32, 3, B_), 256>>>(x, wv, wq, wk);
    cudaFuncSetAttribute(attn_kernel, cudaFuncAttributeMaxDynamicSharedMemorySize, SMEM_SZ);
    attn_kernel<<<dim3(64, B_), 256, SMEM_SZ>>>(x, gamma, beta, mean, var, out);
}

// round 7
// speedup vs baseline: 1.0067x; 1.0067x over previous
#include <cuda_runtime.h>
#include <cuda_fp16.h>
#include <stdint.h>

#define B_ 4
#define C_ 256
#define N_ 4096

// ---------------- device scratch (swizzled tile layouts, attn-ready) --------
__device__ __align__(256) __half g_qt [(size_t)B_ * 64 * 4096]; // 8KB q-tiles [r][qh32|ql32] sw128
__device__ __align__(256) __half g_kt [(size_t)B_ * 64 * 4096]; // 8KB k-tiles
__device__ __align__(256) __half g_vt [(size_t)B_ * 64 * 16384];// 32KB V^T tiles [c][n] sw128

// ---------------- asm helpers ----------------
__device__ __forceinline__ uint32_t smem_u32(const void* p) {
    uint32_t a;
    asm("{ .reg .u64 t; cvta.to.shared.u64 t, %1; cvt.u32.u64 %0, t; }" : "=r"(a) : "l"(p));
    return a;
}
__device__ __forceinline__ void ldsm4(uint32_t* r, uint32_t a) {
    asm volatile("ldmatrix.sync.aligned.m8n8.x4.shared.b16 {%0,%1,%2,%3}, [%4];"
        : "=r"(r[0]), "=r"(r[1]), "=r"(r[2]), "=r"(r[3]) : "r"(a));
}
__device__ __forceinline__ void mma16816(float* c, const uint32_t* a, const uint32_t* b) {
    asm volatile("mma.sync.aligned.m16n8k16.row.col.f32.f16.f16.f32 "
        "{%0,%1,%2,%3}, {%4,%5,%6,%7}, {%8,%9}, {%0,%1,%2,%3};"
        : "+f"(c[0]), "+f"(c[1]), "+f"(c[2]), "+f"(c[3])
        : "r"(a[0]), "r"(a[1]), "r"(a[2]), "r"(a[3]), "r"(b[0]), "r"(b[1]));
}
__device__ __forceinline__ uint32_t pk(float lo, float hi) {
    uint32_t r;
    asm("cvt.rn.f16x2.f32 %0, %1, %2;" : "=r"(r) : "f"(hi), "f"(lo));
    return r;
}
#define MBAR_INIT(m, c) \
    asm volatile("mbarrier.init.shared.b64 [%0], %1;" :: "r"((uint32_t)(m)), "r"((uint32_t)(c)) : "memory")
#define MBAR_EXPECT_TX(m, b) \
    asm volatile("mbarrier.arrive.expect_tx.shared.b64 _, [%0], %1;" :: "r"((uint32_t)(m)), "r"((uint32_t)(b)) : "memory")
#define MBAR_WAIT(m, ph) do { \
    uint32_t _m = (uint32_t)(m), _p = (uint32_t)(ph), _d; \
    asm volatile("{\n\t.reg .pred p;\n\t" \
        "mbarrier.try_wait.parity.acquire.cta.shared::cta.b64 p, [%1], %2;\n\tselp.b32 %0,1,0,p;\n\t}" \
        : "=r"(_d) : "r"(_m), "r"(_p) : "memory"); \
    if (!_d) { asm volatile("{\n\t.reg .pred P1;\n\tWL_%=:\n\t" \
        "mbarrier.try_wait.parity.acquire.cta.shared::cta.b64 P1, [%0], %1, 0x989680;\n\t" \
        "@P1 bra.uni WD_%=;\n\tbra.uni WL_%=;\n\tWD_%=:\n\t}" :: "r"(_m), "r"(_p) : "memory"); } \
} while (0)
__device__ __forceinline__ void bulk_g2s(uint32_t dst, const void* src, uint32_t bytes, uint32_t mbar) {
    asm volatile("cp.async.bulk.shared::cluster.global.mbarrier::complete_tx::bytes [%0], [%1], %2, [%3];"
        :: "r"(dst), "l"(__cvta_generic_to_global(src)), "r"(bytes), "r"(mbar) : "memory");
}

// ---------------------------------------------------------------------------
// Kernel 1: QKV projection (FFMA) writing DIRECTLY into swizzled tile layouts.
// (unchanged from R6 — known correct)
// ---------------------------------------------------------------------------
__global__ __launch_bounds__(256) void qkv_proj_kernel(
    const float* __restrict__ x, const float* __restrict__ wv,
    const float* __restrict__ wq, const float* __restrict__ wk)
{
    const int b = blockIdx.z, nb = blockIdx.x * 128, j0 = blockIdx.y * 128;
    const int tid = threadIdx.x, tyy = tid >> 4, txx = tid & 15;
    __shared__ float xs[16][128];
    __shared__ float ws[16][132];
    float acc[8][8];
#pragma unroll
    for (int i = 0; i < 8; i++)
#pragma unroll
        for (int j = 0; j < 8; j++) acc[i][j] = 0.f;
    const float* xb = x + (size_t)b * C_ * N_;

    for (int c0 = 0; c0 < C_; c0 += 16) {
#pragma unroll
        for (int w = 0; w < 2; w++) {
            int f4 = tid + w * 256, k = f4 >> 5, n4 = f4 & 31;
            *(float4*)(&xs[k][n4 * 4]) = *(const float4*)(xb + (size_t)(c0 + k) * N_ + nb + n4 * 4);
        }
#pragma unroll
        for (int it = 0; it < 8; it++) {
            int jl = (tid >> 4) + it * 16, k = tid & 15, j = j0 + jl, c = c0 + k;
            float v = 0.f;
            if (j < 256) v = wv[j * C_ + c];
            else if (j < 288) v = wq[(j - 256) * C_ + c];
            else if (j < 320) v = wk[(j - 288) * C_ + c];
            ws[k][jl] = v;
        }
        __syncthreads();
#pragma unroll
        for (int k = 0; k < 16; k++) {
            float a[8], bb[8];
            *(float4*)&a[0]  = *(const float4*)&xs[k][tyy * 4];
            *(float4*)&a[4]  = *(const float4*)&xs[k][64 + tyy * 4];
            *(float4*)&bb[0] = *(const float4*)&ws[k][txx * 4];
            *(float4*)&bb[4] = *(const float4*)&ws[k][64 + txx * 4];
#pragma unroll
            for (int i = 0; i < 8; i++)
#pragma unroll
                for (int j = 0; j < 8; j++) acc[i][j] = fmaf(a[i], bb[j], acc[i][j]);
        }
        __syncthreads();
    }

    if (j0 < 256) {
#pragma unroll
        for (int half = 0; half < 2; half++) {
            int n0 = nb + half * 64 + tyy * 4;
            int tkey = n0 >> 6, nl0 = n0 & 63;
            char* tb = (char*)(g_vt + ((size_t)(b * 64 + tkey)) * 16384);
            uint32_t sw = (uint32_t)(nl0 * 2);
#pragma unroll
            for (int g = 0; g < 2; g++)
#pragma unroll
                for (int jj = 0; jj < 4; jj++) {
                    int c = j0 + g * 64 + txx * 4 + jj;
                    __half h[4];
                    h[0] = __float2half_rn(acc[half * 4 + 0][g * 4 + jj]);
                    h[1] = __float2half_rn(acc[half * 4 + 1][g * 4 + jj]);
                    h[2] = __float2half_rn(acc[half * 4 + 2][g * 4 + jj]);
                    h[3] = __float2half_rn(acc[half * 4 + 3][g * 4 + jj]);
                    *(uint2*)(tb + c * 128 + (sw ^ ((c & 7) << 4))) = *(uint2*)h;
                }
        }
    } else {
        const int q4 = txx * 4;
        const bool isQ = q4 < 32;
        const int qc = isQ ? q4 : q4 - 32;
        __half* base = isQ ? g_qt : g_kt;
#pragma unroll
        for (int i = 0; i < 8; i++) {
            int row = nb + ((i < 4) ? (tyy * 4 + i) : (64 + tyy * 4 + i - 4));
            int tq = row >> 6, r = row & 63;
            char* tb = (char*)(base + ((size_t)(b * 64 + tq)) * 4096);
            __half hi[4], lo[4];
#pragma unroll
            for (int jj = 0; jj < 4; jj++) {
                float a = acc[i][jj];
                __half h = __float2half_rn(a);
                hi[jj] = h;
                lo[jj] = __float2half_rn(a - __half2float(h));
            }
            *(uint2*)(tb + r * 128 + ((qc * 2)        ^ ((r & 7) << 4))) = *(uint2*)hi;
            *(uint2*)(tb + r * 128 + (((64 + qc * 2)) ^ ((r & 7) << 4))) = *(uint2*)lo;
        }
    }
}

// ---------------------------------------------------------------------------
// Kernel 2: HMMA flash attention, 512 threads / 16 warps, NO duplicated work.
// Warp (wm = w&3, wc = w>>2): GEMM1 -> S[16wm.., 16wc..] (12 HMMA),
// softmax split 4-way per row (cross-warp stats via smem), P -> smem once,
// GEMM2 -> Y[16wm rows x 64wc cols] (32 HMMA, y regs 8x4).
// ---------------------------------------------------------------------------
#define OFF_RDT 0                 /* 16384 */
#define OFF_Q   16384             /* 8192 */
#define OFF_K   24576             /* 2 x 8192 */
#define OFF_V   40960             /* 2 x 32768 */
#define OFF_P   106496            /* 64 x 72 halves = 9216 */
#define OFF_MX  115712            /* 4 x 64 f32 */
#define OFF_SM  116736            /* 4 x 64 f32 */
#define OFF_BAR 117760
#define SMEM_SZ 117824

__global__ __launch_bounds__(512, 1) void attn_kernel(
    const float* __restrict__ x, const float* __restrict__ gamma,
    const float* __restrict__ beta, const float* __restrict__ mean,
    const float* __restrict__ var, float* __restrict__ out)
{
    extern __shared__ char smc[];
    float* rdt = (float*)(smc + OFF_RDT);
    float* mx  = (float*)(smc + OFF_MX);
    float* smsum = (float*)(smc + OFF_SM);
    const uint32_t sb = smem_u32(smc);
    const uint32_t bar0 = sb + OFF_BAR, bar1 = sb + OFF_BAR + 8;
    const uint32_t sbP = sb + OFF_P;
    const int tid = threadIdx.x, w = tid >> 5, lane = tid & 31;
    const int wm = w & 3, wc = w >> 2;
    const int b = blockIdx.y, qt = blockIdx.x, qb = qt * 64;

    for (int i = tid; i < 4096; i += 512) {
        int dy = i >> 6, dx = i & 63;
        rdt[i] = 1.0f / (sqrtf((float)(dy * dy + dx * dx)) + 1.0f);
    }
    {
        const uint4* qsrc = (const uint4*)(g_qt + ((size_t)(b * 64 + qt)) * 4096);
        ((uint4*)(smc + OFF_Q))[tid] = qsrc[tid];
    }
    if (tid == 0) { MBAR_INIT(bar0, 1); MBAR_INIT(bar1, 1); }
    __syncthreads();

    // persistent Q A-frags (rows 16*wm band, hi/lo, two k-steps)
    uint32_t qf[2][2][4];
#pragma unroll
    for (int hl = 0; hl < 2; hl++)
#pragma unroll
        for (int kk = 0; kk < 2; kk++) {
            int row = wm * 16 + (lane & 7) + ((lane & 8) ? 8 : 0);
            int colb = hl * 64 + kk * 32 + ((lane & 16) ? 16 : 0);
            ldsm4(qf[hl][kk], sb + OFF_Q + row * 128 + (colb ^ ((row & 7) << 4)));
        }

    const __half* kt = g_kt + (size_t)b * 64 * 4096;
    const __half* vt = g_vt + (size_t)b * 64 * 16384;

    // prologue: K(0)+V(0) into stage 0
    if (tid == 0) {
        MBAR_EXPECT_TX(bar0, 40960);
        bulk_g2s(sb + OFF_K, kt, 8192, bar0);
        bulk_g2s(sb + OFF_V, vt, 32768, bar0);
    }

    float y[8][4];
#pragma unroll
    for (int i = 0; i < 8; i++)
#pragma unroll
        for (int j = 0; j < 4; j++) y[i][j] = 0.f;
    float mA = -1e30f, mB = -1e30f, lA = 0.f, lB = 0.f;
    const int rxA = wm * 16 + (lane >> 2), rxB = rxA + 8;
    const int c0 = 2 * (lane & 3);

    for (int t = 0; t < 64; t++) {
        if (tid == 0 && t + 1 < 64) {
            uint32_t st = (t + 1) & 1;
            uint32_t bk = st ? bar1 : bar0;
            MBAR_EXPECT_TX(bk, 40960);
            bulk_g2s(sb + OFF_K + st * 8192,  kt + (size_t)(t + 1) * 4096,  8192,  bk);
            bulk_g2s(sb + OFF_V + st * 32768, vt + (size_t)(t + 1) * 16384, 32768, bk);
        }
        MBAR_WAIT(((t & 1) ? bar1 : bar0), (t >> 1) & 1);

        const uint32_t bK = sb + OFF_K + (t & 1) * 8192;
        const uint32_t bV = sb + OFF_V + (t & 1) * 32768;

        // ---- GEMM1: S block [16 rows wm][16 cols wc], 3-pass hi/lo, 12 HMMA
        float s[2][4];
#pragma unroll
        for (int f = 0; f < 2; f++)
#pragma unroll
            for (int j = 0; j < 4; j++) s[f][j] = 0.f;
#pragma unroll
        for (int kk = 0; kk < 2; kk++) {
            int row = wc * 16 + (lane & 7) + ((lane & 16) ? 8 : 0);
            int colb = kk * 32 + ((lane & 8) ? 16 : 0);
            uint32_t bh[4], bl[4];
            ldsm4(bh, bK + row * 128 + (colb ^ ((row & 7) << 4)));
            ldsm4(bl, bK + row * 128 + ((colb + 64) ^ ((row & 7) << 4)));
            mma16816(s[0], qf[0][kk], bh);
            mma16816(s[1], qf[0][kk], bh + 2);
            mma16816(s[0], qf[1][kk], bh);
            mma16816(s[1], qf[1][kk], bh + 2);
            mma16816(s[0], qf[0][kk], bl);
            mma16816(s[1], qf[0][kk], bl + 2);
        }

        // ---- softmax: distance, warp-local 16-col max, cross-warp combine
        const float* rdtp = rdt + ((qt > t) ? (qt - t) : (t - qt)) * 64;
        float tmA = -1e30f, tmB = -1e30f;
#pragma unroll
        for (int j = 0; j < 2; j++) {
            int c = wc * 16 + j * 8 + c0;
            int d0 = rxA - c;     d0 = d0 < 0 ? -d0 : d0;
            int d1 = rxA - c - 1; d1 = d1 < 0 ? -d1 : d1;
            int d2 = rxB - c;     d2 = d2 < 0 ? -d2 : d2;
            int d3 = rxB - c - 1; d3 = d3 < 0 ? -d3 : d3;
            s[j][0] *= rdtp[d0];
            s[j][1] *= rdtp[d1];
            s[j][2] *= rdtp[d2];
            s[j][3] *= rdtp[d3];
            tmA = fmaxf(tmA, fmaxf(s[j][0], s[j][1]));
            tmB = fmaxf(tmB, fmaxf(s[j][2], s[j][3]));
        }
        tmA = fmaxf(tmA, __shfl_xor_sync(0xffffffffu, tmA, 1));
        tmA = fmaxf(tmA, __shfl_xor_sync(0xffffffffu, tmA, 2));
        tmB = fmaxf(tmB, __shfl_xor_sync(0xffffffffu, tmB, 1));
        tmB = fmaxf(tmB, __shfl_xor_sync(0xffffffffu, tmB, 2));
        if ((lane & 3) == 0) {
            mx[wc * 64 + rxA] = tmA;
            mx[wc * 64 + rxB] = tmB;
        }
        __syncthreads();
        float gmA = fmaxf(fmaxf(mx[rxA], mx[64 + rxA]), fmaxf(mx[128 + rxA], mx[192 + rxA]));
        float gmB = fmaxf(fmaxf(mx[rxB], mx[64 + rxB]), fmaxf(mx[128 + rxB], mx[192 + rxB]));
        float mnA = fmaxf(mA, gmA), mnB = fmaxf(mB, gmB);
        float scA = __expf(mA - mnA), scB = __expf(mB - mnB);
        mA = mnA; mB = mnB;
        if (!__all_sync(0xffffffffu, (scA == 1.f) && (scB == 1.f))) {
            lA *= scA; lB *= scB;
#pragma unroll
            for (int nt = 0; nt < 8; nt++) {
                y[nt][0] *= scA; y[nt][1] *= scA;
                y[nt][2] *= scB; y[nt][3] *= scB;
            }
        }
        float sumA = 0.f, sumB = 0.f;
#pragma unroll
        for (int j = 0; j < 2; j++) {
            float p0 = __expf(s[j][0] - mnA), p1 = __expf(s[j][1] - mnA);
            float p2 = __expf(s[j][2] - mnB), p3 = __expf(s[j][3] - mnB);
            sumA += p0 + p1; sumB += p2 + p3;
            int c = wc * 16 + j * 8 + c0;
            *(uint32_t*)(smc + OFF_P + (rxA * 72 + c) * 2) = pk(p0, p1);
            *(uint32_t*)(smc + OFF_P + (rxB * 72 + c) * 2) = pk(p2, p3);
        }
        sumA += __shfl_xor_sync(0xffffffffu, sumA, 1);
        sumA += __shfl_xor_sync(0xffffffffu, sumA, 2);
        sumB += __shfl_xor_sync(0xffffffffu, sumB, 1);
        sumB += __shfl_xor_sync(0xffffffffu, sumB, 2);
        if ((lane & 3) == 0) {
            smsum[wc * 64 + rxA] = sumA;
            smsum[wc * 64 + rxB] = sumB;
        }
        __syncthreads();   // P + partial sums visible
        lA += smsum[rxA] + smsum[64 + rxA] + smsum[128 + rxA] + smsum[192 + rxA];
        lB += smsum[rxB] + smsum[64 + rxB] + smsum[128 + rxB] + smsum[192 + rxB];

        // ---- GEMM2: Y[16 rows wm][64 cols wc] += P * V^T  (32 HMMA)
#pragma unroll
        for (int kk = 0; kk < 4; kk++) {
            uint32_t pa[4];
            int prow = wm * 16 + (lane & 7) + ((lane & 8) ? 8 : 0);
            int pcol = kk * 16 + ((lane & 16) ? 8 : 0);
            ldsm4(pa, sbP + (prow * 72 + pcol) * 2);
#pragma unroll
            for (int np = 0; np < 4; np++) {
                int row = wc * 64 + np * 16 + (lane & 7) + ((lane & 16) ? 8 : 0);
                int colb = kk * 32 + ((lane & 8) ? 16 : 0);
                uint32_t bv[4];
                ldsm4(bv, bV + row * 128 + (colb ^ ((row & 7) << 4)));
                mma16816(y[np*2],   pa, bv);
                mma16816(y[np*2+1], pa, bv + 2);
            }
        }
        __syncthreads();   // stage + P/stat buffer reuse guard
    }

    // ---- epilogue: normalize, transpose via smem, BN + ReLU + residual
    float* Ys = (float*)smc;     // [64][257] f32 (overlaps rdt/Q/K/V; all dead)
    float rA = 1.f / lA, rB = 1.f / lB;
#pragma unroll
    for (int nt = 0; nt < 8; nt++) {
        int c = wc * 64 + nt * 8 + c0;
        Ys[rxA * 257 + c]     = y[nt][0] * rA;
        Ys[rxA * 257 + c + 1] = y[nt][1] * rA;
        Ys[rxB * 257 + c]     = y[nt][2] * rB;
        Ys[rxB * 257 + c + 1] = y[nt][3] * rB;
    }
    __syncthreads();
    const int n = tid & 63, cg = tid >> 6;
#pragma unroll 4
    for (int it = 0; it < 32; it++) {
        int c = it * 8 + cg;
        float inv = gamma[c] * rsqrtf(var[c] + 1e-5f);
        float add = fmaf(-mean[c], inv, beta[c]);
        size_t idx = ((size_t)b * C_ + c) * N_ + qb + n;
        float yv = Ys[n * 257 + c];
        out[idx] = fmaxf(fmaf(yv, inv, add), 0.f) + x[idx];
    }
}

// ---------------------------------------------------------------------------
extern "C" void kernel_launch(void* const* d_in, const int* in_sizes, int n_in,
                              void* d_out, int out_size)
{
    (void)in_sizes; (void)n_in; (void)out_size;
    const float* x     = (const float*)d_in[0];
    const float* wv    = (const float*)d_in[1];
    const float* wq    = (const float*)d_in[2];
    const float* wk    = (const float*)d_in[3];
    const float* gamma = (const float*)d_in[4];
    const float* beta  = (const float*)d_in[5];
    const float* mean  = (const float*)d_in[6];
    const float* var   = (const float*)d_in[7];
    float* out = (float*)d_out;

    qkv_proj_kernel<<<dim3(32, 3, B_), 256>>>(x, wv, wq, wk);
    cudaFuncSetAttribute(attn_kernel, cudaFuncAttributeMaxDynamicSharedMemorySize, SMEM_SZ);
    attn_kernel<<<dim3(64, B_), 512, SMEM_SZ>>>(x, gamma, beta, mean, var, out);
}

// round 8
// speedup vs baseline: 1.1152x; 1.1078x over previous
#include <cuda_runtime.h>
#include <cuda_fp16.h>
#include <stdint.h>

#define B_ 4
#define C_ 256
#define N_ 4096

// ---------------- device scratch (swizzled tile layouts, attn-ready) --------
__device__ __align__(256) __half g_qt [(size_t)B_ * 64 * 4096]; // 8KB q-tiles [r][qh32|ql32] sw128
__device__ __align__(256) __half g_kt [(size_t)B_ * 64 * 4096]; // 8KB k-tiles
__device__ __align__(256) __half g_vt [(size_t)B_ * 64 * 16384];// 32KB V^T tiles [c][n] sw128

// ---------------- asm helpers ----------------
__device__ __forceinline__ uint32_t smem_u32(const void* p) {
    uint32_t a;
    asm("{ .reg .u64 t; cvta.to.shared.u64 t, %1; cvt.u32.u64 %0, t; }" : "=r"(a) : "l"(p));
    return a;
}
__device__ __forceinline__ void ldsm4(uint32_t* r, uint32_t a) {
    asm volatile("ldmatrix.sync.aligned.m8n8.x4.shared.b16 {%0,%1,%2,%3}, [%4];"
        : "=r"(r[0]), "=r"(r[1]), "=r"(r[2]), "=r"(r[3]) : "r"(a));
}
__device__ __forceinline__ void mma16816(float* c, const uint32_t* a, const uint32_t* b) {
    asm volatile("mma.sync.aligned.m16n8k16.row.col.f32.f16.f16.f32 "
        "{%0,%1,%2,%3}, {%4,%5,%6,%7}, {%8,%9}, {%0,%1,%2,%3};"
        : "+f"(c[0]), "+f"(c[1]), "+f"(c[2]), "+f"(c[3])
        : "r"(a[0]), "r"(a[1]), "r"(a[2]), "r"(a[3]), "r"(b[0]), "r"(b[1]));
}
__device__ __forceinline__ uint32_t pk(float lo, float hi) {
    uint32_t r;
    asm("cvt.rn.f16x2.f32 %0, %1, %2;" : "=r"(r) : "f"(hi), "f"(lo));
    return r;
}
#define MBAR_INIT(m, c) \
    asm volatile("mbarrier.init.shared.b64 [%0], %1;" :: "r"((uint32_t)(m)), "r"((uint32_t)(c)) : "memory")
#define MBAR_EXPECT_TX(m, b) \
    asm volatile("mbarrier.arrive.expect_tx.shared.b64 _, [%0], %1;" :: "r"((uint32_t)(m)), "r"((uint32_t)(b)) : "memory")
#define MBAR_WAIT(m, ph) do { \
    uint32_t _m = (uint32_t)(m), _p = (uint32_t)(ph), _d; \
    asm volatile("{\n\t.reg .pred p;\n\t" \
        "mbarrier.try_wait.parity.acquire.cta.shared::cta.b64 p, [%1], %2;\n\tselp.b32 %0,1,0,p;\n\t}" \
        : "=r"(_d) : "r"(_m), "r"(_p) : "memory"); \
    if (!_d) { asm volatile("{\n\t.reg .pred P1;\n\tWL_%=:\n\t" \
        "mbarrier.try_wait.parity.acquire.cta.shared::cta.b64 P1, [%0], %1, 0x989680;\n\t" \
        "@P1 bra.uni WD_%=;\n\tbra.uni WL_%=;\n\tWD_%=:\n\t}" :: "r"(_m), "r"(_p) : "memory"); } \
} while (0)
__device__ __forceinline__ void bulk_g2s(uint32_t dst, const void* src, uint32_t bytes, uint32_t mbar) {
    asm volatile("cp.async.bulk.shared::cluster.global.mbarrier::complete_tx::bytes [%0], [%1], %2, [%3];"
        :: "r"(dst), "l"(__cvta_generic_to_global(src)), "r"(bytes), "r"(mbar) : "memory");
}

// ---------------------------------------------------------------------------
// Kernel 1: QKV projection (FFMA) writing DIRECTLY into swizzled tile layouts.
// (math unchanged from R6 — known correct; launch_bounds -> occupancy 2)
// ---------------------------------------------------------------------------
__global__ __launch_bounds__(256, 2) void qkv_proj_kernel(
    const float* __restrict__ x, const float* __restrict__ wv,
    const float* __restrict__ wq, const float* __restrict__ wk)
{
    const int b = blockIdx.z, nb = blockIdx.x * 128, j0 = blockIdx.y * 128;
    const int tid = threadIdx.x, tyy = tid >> 4, txx = tid & 15;
    __shared__ float xs[16][128];
    __shared__ float ws[16][132];
    float acc[8][8];
#pragma unroll
    for (int i = 0; i < 8; i++)
#pragma unroll
        for (int j = 0; j < 8; j++) acc[i][j] = 0.f;
    const float* xb = x + (size_t)b * C_ * N_;

    for (int c0 = 0; c0 < C_; c0 += 16) {
#pragma unroll
        for (int w = 0; w < 2; w++) {
            int f4 = tid + w * 256, k = f4 >> 5, n4 = f4 & 31;
            *(float4*)(&xs[k][n4 * 4]) = *(const float4*)(xb + (size_t)(c0 + k) * N_ + nb + n4 * 4);
        }
#pragma unroll
        for (int it = 0; it < 8; it++) {
            int jl = (tid >> 4) + it * 16, k = tid & 15, j = j0 + jl, c = c0 + k;
            float v = 0.f;
            if (j < 256) v = wv[j * C_ + c];
            else if (j < 288) v = wq[(j - 256) * C_ + c];
            else if (j < 320) v = wk[(j - 288) * C_ + c];
            ws[k][jl] = v;
        }
        __syncthreads();
#pragma unroll
        for (int k = 0; k < 16; k++) {
            float a[8], bb[8];
            *(float4*)&a[0]  = *(const float4*)&xs[k][tyy * 4];
            *(float4*)&a[4]  = *(const float4*)&xs[k][64 + tyy * 4];
            *(float4*)&bb[0] = *(const float4*)&ws[k][txx * 4];
            *(float4*)&bb[4] = *(const float4*)&ws[k][64 + txx * 4];
#pragma unroll
            for (int i = 0; i < 8; i++)
#pragma unroll
                for (int j = 0; j < 8; j++) acc[i][j] = fmaf(a[i], bb[j], acc[i][j]);
        }
        __syncthreads();
    }

    if (j0 < 256) {
#pragma unroll
        for (int half = 0; half < 2; half++) {
            int n0 = nb + half * 64 + tyy * 4;
            int tkey = n0 >> 6, nl0 = n0 & 63;
            char* tb = (char*)(g_vt + ((size_t)(b * 64 + tkey)) * 16384);
            uint32_t sw = (uint32_t)(nl0 * 2);
#pragma unroll
            for (int g = 0; g < 2; g++)
#pragma unroll
                for (int jj = 0; jj < 4; jj++) {
                    int c = j0 + g * 64 + txx * 4 + jj;
                    __half h[4];
                    h[0] = __float2half_rn(acc[half * 4 + 0][g * 4 + jj]);
                    h[1] = __float2half_rn(acc[half * 4 + 1][g * 4 + jj]);
                    h[2] = __float2half_rn(acc[half * 4 + 2][g * 4 + jj]);
                    h[3] = __float2half_rn(acc[half * 4 + 3][g * 4 + jj]);
                    *(uint2*)(tb + c * 128 + (sw ^ ((c & 7) << 4))) = *(uint2*)h;
                }
        }
    } else {
        const int q4 = txx * 4;
        const bool isQ = q4 < 32;
        const int qc = isQ ? q4 : q4 - 32;
        __half* base = isQ ? g_qt : g_kt;
#pragma unroll
        for (int i = 0; i < 8; i++) {
            int row = nb + ((i < 4) ? (tyy * 4 + i) : (64 + tyy * 4 + i - 4));
            int tq = row >> 6, r = row & 63;
            char* tb = (char*)(base + ((size_t)(b * 64 + tq)) * 4096);
            __half hi[4], lo[4];
#pragma unroll
            for (int jj = 0; jj < 4; jj++) {
                float a = acc[i][jj];
                __half h = __float2half_rn(a);
                hi[jj] = h;
                lo[jj] = __float2half_rn(a - __half2float(h));
            }
            *(uint2*)(tb + r * 128 + ((qc * 2)        ^ ((r & 7) << 4))) = *(uint2*)hi;
            *(uint2*)(tb + r * 128 + (((64 + qc * 2)) ^ ((r & 7) << 4))) = *(uint2*)lo;
        }
    }
}

// ---------------------------------------------------------------------------
// Kernel 2: HMMA flash attention, 32-row q-tiles, 256 threads, 2 CTAs/SM.
// Warp (wm = w&1: 16-row band, wc = w>>1: col quarter):
//   GEMM1 -> S[16 x 16]  (12 HMMA, 3-pass hi/lo)
//   softmax: warp-local 16-col stats, 4-way cross-warp max via smem
//   P -> smem (pitch 72 halves), GEMM2 -> Y[16 x 64] (32 HMMA, y[8][4])
// l-partials kept in registers, combined once at the end.
// ---------------------------------------------------------------------------
#define OFF_P   0          /* 32 x 144B = 4608 (also Q staging: 4096) */
#define OFF_RDT 4608       /* 16384 */
#define OFF_K   20992      /* 2 x 8192 */
#define OFF_V   37376      /* 2 x 32768 */
#define OFF_MX  102912     /* 4 x 32 f32 */
#define OFF_LS  103424     /* 4 x 32 f32 */
#define OFF_BAR 103936
#define SMEM_SZ 104064

__global__ __launch_bounds__(256, 2) void attn_kernel(
    const float* __restrict__ x, const float* __restrict__ gamma,
    const float* __restrict__ beta, const float* __restrict__ mean,
    const float* __restrict__ var, float* __restrict__ out)
{
    extern __shared__ char smc[];
    float* rdt = (float*)(smc + OFF_RDT);
    float* mx  = (float*)(smc + OFF_MX);
    float* ls  = (float*)(smc + OFF_LS);
    const uint32_t sb = smem_u32(smc);
    const uint32_t bar0 = sb + OFF_BAR, bar1 = sb + OFF_BAR + 8;
    const uint32_t sbP = sb + OFF_P;
    const int tid = threadIdx.x, w = tid >> 5, lane = tid & 31;
    const int wm = w & 1, wc = w >> 1;
    const int b = blockIdx.y, qt = blockIdx.x, qb = qt * 32;

    for (int i = tid; i < 4096; i += 256) {
        int dy = i >> 6, dx = i & 63;
        rdt[i] = 1.0f / (sqrtf((float)(dy * dy + dx * dx)) + 1.0f);
    }
    if (tid == 0) { MBAR_INIT(bar0, 1); MBAR_INIT(bar1, 1); }
    {   // Q staging: 32 rows x 128B slice of the 64-row swizzled q-tile
        const char* qsrc = (const char*)(g_qt + ((size_t)(b * 64 + (qt >> 1))) * 4096)
                         + (size_t)(qt & 1) * 32 * 128;
        ((uint4*)smc)[tid] = ((const uint4*)qsrc)[tid];
    }
    __syncthreads();

    // persistent Q A-frags
    uint32_t qf[2][2][4];
#pragma unroll
    for (int hl = 0; hl < 2; hl++)
#pragma unroll
        for (int kk = 0; kk < 2; kk++) {
            int row = wm * 16 + (lane & 7) + ((lane & 8) ? 8 : 0);
            int colb = hl * 64 + kk * 32 + ((lane & 16) ? 16 : 0);
            ldsm4(qf[hl][kk], sbP + row * 128 + (colb ^ ((row & 7) << 4)));
        }

    const __half* kt = g_kt + (size_t)b * 64 * 4096;
    const __half* vt = g_vt + (size_t)b * 64 * 16384;

    if (tid == 0) {      // prologue: K(0)+V(0) into stage 0
        MBAR_EXPECT_TX(bar0, 40960);
        bulk_g2s(sb + OFF_K, kt, 8192, bar0);
        bulk_g2s(sb + OFF_V, vt, 32768, bar0);
    }
    __syncthreads();     // qf loads done before any P writes

    float y[8][4];
#pragma unroll
    for (int i = 0; i < 8; i++)
#pragma unroll
        for (int j = 0; j < 4; j++) y[i][j] = 0.f;
    float mA = -1e30f, mB = -1e30f, lA = 0.f, lB = 0.f;
    const int rxA = wm * 16 + (lane >> 2), rxB = rxA + 8;   // local rows 0..31
    const int c0 = 2 * (lane & 3);
    const int rxAi = (qt & 1) * 32 + rxA, rxBi = rxAi + 8;  // image x coords
    const int ry = qt >> 1;

    for (int t = 0; t < 64; t++) {
        MBAR_WAIT(((t & 1) ? bar1 : bar0), (t >> 1) & 1);
        const uint32_t bK = sb + OFF_K + (t & 1) * 8192;
        const uint32_t bV = sb + OFF_V + (t & 1) * 32768;

        // ---- GEMM1: S[16 rows wm][16 cols wc], 3-pass hi/lo, 12 HMMA
        float s[2][4];
#pragma unroll
        for (int f = 0; f < 2; f++)
#pragma unroll
            for (int j = 0; j < 4; j++) s[f][j] = 0.f;
        {
            int krow = wc * 16 + (lane & 7) + ((lane & 16) ? 8 : 0);
#pragma unroll
            for (int kk = 0; kk < 2; kk++) {
                int colb = kk * 32 + ((lane & 8) ? 16 : 0);
                uint32_t bh[4], bl[4];
                ldsm4(bh, bK + krow * 128 + (colb ^ ((krow & 7) << 4)));
                ldsm4(bl, bK + krow * 128 + ((colb + 64) ^ ((krow & 7) << 4)));
                mma16816(s[0], qf[0][kk], bh);
                mma16816(s[1], qf[0][kk], bh + 2);
                mma16816(s[0], qf[1][kk], bh);
                mma16816(s[1], qf[1][kk], bh + 2);
                mma16816(s[0], qf[0][kk], bl);
                mma16816(s[1], qf[0][kk], bl + 2);
            }
        }

        // ---- distance + warp-local max over this warp's 16 cols
        const float* rdtp = rdt + ((ry > t) ? (ry - t) : (t - ry)) * 64;
        float tmA = -1e30f, tmB = -1e30f;
#pragma unroll
        for (int j = 0; j < 2; j++) {
            int c = wc * 16 + j * 8 + c0;
            int d0 = rxAi - c;     d0 = d0 < 0 ? -d0 : d0;
            int d1 = rxAi - c - 1; d1 = d1 < 0 ? -d1 : d1;
            int d2 = rxBi - c;     d2 = d2 < 0 ? -d2 : d2;
            int d3 = rxBi - c - 1; d3 = d3 < 0 ? -d3 : d3;
            s[j][0] *= rdtp[d0];
            s[j][1] *= rdtp[d1];
            s[j][2] *= rdtp[d2];
            s[j][3] *= rdtp[d3];
            tmA = fmaxf(tmA, fmaxf(s[j][0], s[j][1]));
            tmB = fmaxf(tmB, fmaxf(s[j][2], s[j][3]));
        }
        tmA = fmaxf(tmA, __shfl_xor_sync(0xffffffffu, tmA, 1));
        tmA = fmaxf(tmA, __shfl_xor_sync(0xffffffffu, tmA, 2));
        tmB = fmaxf(tmB, __shfl_xor_sync(0xffffffffu, tmB, 1));
        tmB = fmaxf(tmB, __shfl_xor_sync(0xffffffffu, tmB, 2));
        if ((lane & 3) == 0) {
            mx[wc * 32 + rxA] = tmA;
            mx[wc * 32 + rxB] = tmB;
        }
        __syncthreads();   // stats visible; also: all GEMM2(t-1) reads done

        // prefetch t+1 into the stage just freed
        if (tid == 0 && t + 1 < 64) {
            uint32_t st = (t + 1) & 1;
            uint32_t bk = st ? bar1 : bar0;
            MBAR_EXPECT_TX(bk, 40960);
            bulk_g2s(sb + OFF_K + st * 8192,  kt + (size_t)(t + 1) * 4096,  8192,  bk);
            bulk_g2s(sb + OFF_V + st * 32768, vt + (size_t)(t + 1) * 16384, 32768, bk);
        }

        float gmA = fmaxf(fmaxf(mx[rxA], mx[32 + rxA]), fmaxf(mx[64 + rxA], mx[96 + rxA]));
        float gmB = fmaxf(fmaxf(mx[rxB], mx[32 + rxB]), fmaxf(mx[64 + rxB], mx[96 + rxB]));
        float mnA = fmaxf(mA, gmA), mnB = fmaxf(mB, gmB);
        float scA = __expf(mA - mnA), scB = __expf(mB - mnB);
        mA = mnA; mB = mnB;
        if (!__all_sync(0xffffffffu, (scA == 1.f) && (scB == 1.f))) {
            lA *= scA; lB *= scB;
#pragma unroll
            for (int nt = 0; nt < 8; nt++) {
                y[nt][0] *= scA; y[nt][1] *= scA;
                y[nt][2] *= scB; y[nt][3] *= scB;
            }
        }
        float sumA = 0.f, sumB = 0.f;
#pragma unroll
        for (int j = 0; j < 2; j++) {
            float p0 = __expf(s[j][0] - mnA), p1 = __expf(s[j][1] - mnA);
            float p2 = __expf(s[j][2] - mnB), p3 = __expf(s[j][3] - mnB);
            sumA += p0 + p1; sumB += p2 + p3;
            int c = wc * 16 + j * 8 + c0;
            *(uint32_t*)(smc + OFF_P + (rxA * 72 + c) * 2) = pk(p0, p1);
            *(uint32_t*)(smc + OFF_P + (rxB * 72 + c) * 2) = pk(p2, p3);
        }
        sumA += __shfl_xor_sync(0xffffffffu, sumA, 1);
        sumA += __shfl_xor_sync(0xffffffffu, sumA, 2);
        sumB += __shfl_xor_sync(0xffffffffu, sumB, 1);
        sumB += __shfl_xor_sync(0xffffffffu, sumB, 2);
        lA += sumA; lB += sumB;     // per-warp partial (this warp's 16 cols)
        __syncthreads();            // P visible

        // ---- GEMM2: Y[16 rows wm][64 cols wc] += P * V^T  (32 HMMA)
#pragma unroll
        for (int kk = 0; kk < 4; kk++) {
            uint32_t pa[4];
            int prow = wm * 16 + (lane & 7) + ((lane & 8) ? 8 : 0);
            int pcol = kk * 16 + ((lane & 16) ? 8 : 0);
            ldsm4(pa, sbP + (prow * 72 + pcol) * 2);
#pragma unroll
            for (int np = 0; np < 4; np++) {
                int vrow = wc * 64 + np * 16 + (lane & 7) + ((lane & 16) ? 8 : 0);
                int colb = kk * 32 + ((lane & 8) ? 16 : 0);
                uint32_t bv[4];
                ldsm4(bv, bV + vrow * 128 + (colb ^ ((vrow & 7) << 4)));
                mma16816(y[np*2],   pa, bv);
                mma16816(y[np*2+1], pa, bv + 2);
            }
        }
    }

    // ---- combine l partials across the 4 wc groups
    if ((lane & 3) == 0) {
        ls[wc * 32 + rxA] = lA;
        ls[wc * 32 + rxB] = lB;
    }
    __syncthreads();   // also: all GEMM2(63) smem reads done
    const float rlA = 1.f / (ls[rxA] + ls[32 + rxA] + ls[64 + rxA] + ls[96 + rxA]);
    const float rlB = 1.f / (ls[rxB] + ls[32 + rxB] + ls[64 + rxB] + ls[96 + rxB]);

    // ---- epilogue: normalize, transpose via smem, BN + ReLU + residual
    float* Ys = (float*)smc;   // [32][260] f32 = 33280 B (P/rdt/K dead)
#pragma unroll
    for (int nt = 0; nt < 8; nt++) {
        int c = wc * 64 + (nt >> 1) * 16 + (nt & 1) * 8 + c0;
        Ys[rxA * 260 + c]     = y[nt][0] * rlA;
        Ys[rxA * 260 + c + 1] = y[nt][1] * rlA;
        Ys[rxB * 260 + c]     = y[nt][2] * rlB;
        Ys[rxB * 260 + c + 1] = y[nt][3] * rlB;
    }
    __syncthreads();
    const int n = tid & 31, cg = tid >> 5;
#pragma unroll 4
    for (int it = 0; it < 32; it++) {
        int c = it * 8 + cg;
        float inv = gamma[c] * rsqrtf(var[c] + 1e-5f);
        float add = fmaf(-mean[c], inv, beta[c]);
        size_t idx = ((size_t)b * C_ + c) * N_ + qb + n;
        float yv = Ys[n * 260 + c];
        out[idx] = fmaxf(fmaf(yv, inv, add), 0.f) + x[idx];
    }
}

// ---------------------------------------------------------------------------
extern "C" void kernel_launch(void* const* d_in, const int* in_sizes, int n_in,
                              void* d_out, int out_size)
{
    (void)in_sizes; (void)n_in; (void)out_size;
    const float* x     = (const float*)d_in[0];
    const float* wv    = (const float*)d_in[1];
    const float* wq    = (const float*)d_in[2];
    const float* wk    = (const float*)d_in[3];
    const float* gamma = (const float*)d_in[4];
    const float* beta  = (const float*)d_in[5];
    const float* mean  = (const float*)d_in[6];
    const float* var   = (const float*)d_in[7];
    float* out = (float*)d_out;

    qkv_proj_kernel<<<dim3(32, 3, B_), 256>>>(x, wv, wq, wk);
    cudaFuncSetAttribute(attn_kernel, cudaFuncAttributeMaxDynamicSharedMemorySize, SMEM_SZ);
    attn_kernel<<<dim3(128, B_), 256, SMEM_SZ>>>(x, gamma, beta, mean, var, out);
}

// round 9
// speedup vs baseline: 1.4463x; 1.2969x over previous
#include <cuda_runtime.h>
#include <cuda_fp16.h>
#include <stdint.h>

#define B_ 4
#define C_ 256
#define N_ 4096

// ---------------- device scratch (swizzled tile layouts, attn-ready) --------
__device__ __align__(256) __half g_qt [(size_t)B_ * 64 * 4096]; // 8KB q-tiles [r][qh32|ql32] sw128
__device__ __align__(256) __half g_kt [(size_t)B_ * 64 * 4096]; // 8KB k-tiles
__device__ __align__(256) __half g_vt [(size_t)B_ * 64 * 16384];// 32KB V^T tiles [c][n] sw128

// ---------------- asm helpers ----------------
__device__ __forceinline__ uint32_t smem_u32(const void* p) {
    uint32_t a;
    asm("{ .reg .u64 t; cvta.to.shared.u64 t, %1; cvt.u32.u64 %0, t; }" : "=r"(a) : "l"(p));
    return a;
}
__device__ __forceinline__ void ldsm4(uint32_t* r, uint32_t a) {
    asm volatile("ldmatrix.sync.aligned.m8n8.x4.shared.b16 {%0,%1,%2,%3}, [%4];"
        : "=r"(r[0]), "=r"(r[1]), "=r"(r[2]), "=r"(r[3]) : "r"(a));
}
__device__ __forceinline__ void mma16816(float* c, const uint32_t* a, const uint32_t* b) {
    asm volatile("mma.sync.aligned.m16n8k16.row.col.f32.f16.f16.f32 "
        "{%0,%1,%2,%3}, {%4,%5,%6,%7}, {%8,%9}, {%0,%1,%2,%3};"
        : "+f"(c[0]), "+f"(c[1]), "+f"(c[2]), "+f"(c[3])
        : "r"(a[0]), "r"(a[1]), "r"(a[2]), "r"(a[3]), "r"(b[0]), "r"(b[1]));
}
__device__ __forceinline__ uint32_t pk(float lo, float hi) {
    uint32_t r;
    asm("cvt.rn.f16x2.f32 %0, %1, %2;" : "=r"(r) : "f"(hi), "f"(lo));
    return r;
}
#define MBAR_INIT(m, c) \
    asm volatile("mbarrier.init.shared.b64 [%0], %1;" :: "r"((uint32_t)(m)), "r"((uint32_t)(c)) : "memory")
#define MBAR_EXPECT_TX(m, b) \
    asm volatile("mbarrier.arrive.expect_tx.shared.b64 _, [%0], %1;" :: "r"((uint32_t)(m)), "r"((uint32_t)(b)) : "memory")
#define MBAR_WAIT(m, ph) do { \
    uint32_t _m = (uint32_t)(m), _p = (uint32_t)(ph), _d; \
    asm volatile("{\n\t.reg .pred p;\n\t" \
        "mbarrier.try_wait.parity.acquire.cta.shared::cta.b64 p, [%1], %2;\n\tselp.b32 %0,1,0,p;\n\t}" \
        : "=r"(_d) : "r"(_m), "r"(_p) : "memory"); \
    if (!_d) { asm volatile("{\n\t.reg .pred P1;\n\tWL_%=:\n\t" \
        "mbarrier.try_wait.parity.acquire.cta.shared::cta.b64 P1, [%0], %1, 0x989680;\n\t" \
        "@P1 bra.uni WD_%=;\n\tbra.uni WL_%=;\n\tWD_%=:\n\t}" :: "r"(_m), "r"(_p) : "memory"); } \
} while (0)
__device__ __forceinline__ void bulk_g2s(uint32_t dst, const void* src, uint32_t bytes, uint32_t mbar) {
    asm volatile("cp.async.bulk.shared::cluster.global.mbarrier::complete_tx::bytes [%0], [%1], %2, [%3];"
        :: "r"(dst), "l"(__cvta_generic_to_global(src)), "r"(bytes), "r"(mbar) : "memory");
}

// ---------------------------------------------------------------------------
// Kernel 1: HMMA projection.  C[n][j] = sum_c x[c][n] * W[j][c]
// grid (n-tiles 64, jt 0..4, b).  jt<4: V channels j0=jt*64 (2-pass: xh*wh + xl*wh).
// jt==4: Q (j<32) / K (j>=32) channels (3-pass: + xh*wl).
// Warp (wn=w&3: 16 n-rows, wj=w>>2: 32 j-cols). acc[4][4].
// ---------------------------------------------------------------------------
#define PJ_WH  0          /* [64j][64c] fp16 sw128 = 8192 */
#define PJ_WL  8192       /* 8192 (QK only) */
#define PJ_X32 16384      /* [64c][68] fp32 = 17408 */
#define PJ_XH  33792      /* [64n][72c] fp16 pitch 144B = 9216 (reused as V stage) */
#define PJ_XL  43008      /* 9216 */
#define PJ_SZ  52224

__global__ __launch_bounds__(256, 2) void proj_kernel(
    const float* __restrict__ x, const float* __restrict__ wv,
    const float* __restrict__ wq, const float* __restrict__ wk)
{
    extern __shared__ char smc[];
    float* xs32 = (float*)(smc + PJ_X32);
    const uint32_t sb = smem_u32(smc);
    const int tid = threadIdx.x, w = tid >> 5, lane = tid & 31;
    const int wn = w & 3, wj = w >> 2;
    const int b = blockIdx.z, n0 = blockIdx.x * 64, jt = blockIdx.y;
    const bool isQK = (jt == 4);

    float acc[4][4];
#pragma unroll
    for (int i = 0; i < 4; i++)
#pragma unroll
        for (int j = 0; j < 4; j++) acc[i][j] = 0.f;

    for (int c0 = 0; c0 < 256; c0 += 64) {
        __syncthreads();   // prior chunk's ldsm reads done
        // ---- W chunk: 64j x 64c fp32 -> wh (+ wl if QK), sw128 rows
#pragma unroll
        for (int it = 0; it < 4; it++) {
            int f4 = tid + it * 256;
            int jl = f4 >> 4, c4 = f4 & 15;
            const float* src;
            if (!isQK) src = wv + (size_t)(jt * 64 + jl) * 256 + c0 + c4 * 4;
            else src = ((jl < 32) ? (wq + (size_t)jl * 256) : (wk + (size_t)(jl - 32) * 256)) + c0 + c4 * 4;
            float4 v = *(const float4*)src;
            __half h[4];
            h[0] = __float2half_rn(v.x); h[1] = __float2half_rn(v.y);
            h[2] = __float2half_rn(v.z); h[3] = __float2half_rn(v.w);
            *(uint2*)(smc + PJ_WH + jl * 128 + ((c4 * 8) ^ ((jl & 7) << 4))) = *(uint2*)h;
            if (isQK) {
                __half l[4];
                l[0] = __float2half_rn(v.x - __half2float(h[0]));
                l[1] = __float2half_rn(v.y - __half2float(h[1]));
                l[2] = __float2half_rn(v.z - __half2float(h[2]));
                l[3] = __float2half_rn(v.w - __half2float(h[3]));
                *(uint2*)(smc + PJ_WL + jl * 128 + ((c4 * 8) ^ ((jl & 7) << 4))) = *(uint2*)l;
            }
        }
        // ---- x chunk [64c][64n] fp32 coalesced -> xs32 (pitch 68)
#pragma unroll
        for (int it = 0; it < 4; it++) {
            int f4 = tid + it * 256;
            int cl = f4 >> 4, n4 = f4 & 15;
            float4 v = *(const float4*)(x + (size_t)(b * 256 + c0 + cl) * 4096 + n0 + n4 * 4);
            *(float4*)(xs32 + cl * 68 + n4 * 4) = v;
        }
        __syncthreads();
        // ---- register transpose + hi/lo convert: xs32[c][n] -> xh/xl [n][c]
        {
            int n = tid & 63, cq = tid >> 6;
#pragma unroll
            for (int i = 0; i < 4; i++) {
                int c = cq * 16 + i * 4;
                __half h[4], l[4];
#pragma unroll
                for (int k2 = 0; k2 < 4; k2++) {
                    float f = xs32[(c + k2) * 68 + n];
                    h[k2] = __float2half_rn(f);
                    l[k2] = __float2half_rn(f - __half2float(h[k2]));
                }
                *(uint2*)(smc + PJ_XH + n * 144 + c * 2) = *(uint2*)h;
                *(uint2*)(smc + PJ_XL + n * 144 + c * 2) = *(uint2*)l;
            }
        }
        __syncthreads();
        // ---- MMA: 4 k-steps of 16
#pragma unroll
        for (int kk = 0; kk < 4; kk++) {
            uint32_t ah[4], al[4];
            int arow = wn * 16 + (lane & 7) + ((lane & 8) ? 8 : 0);
            int aoff = arow * 144 + kk * 32 + ((lane & 16) ? 16 : 0);
            ldsm4(ah, sb + PJ_XH + aoff);
            ldsm4(al, sb + PJ_XL + aoff);
            int jr0 = wj * 32 + (lane & 7) + ((lane & 16) ? 8 : 0);
            int bcol = kk * 32 + ((lane & 8) ? 16 : 0);
#pragma unroll
            for (int nt2 = 0; nt2 < 2; nt2++) {
                int jrow = jr0 + nt2 * 16;
                uint32_t bh[4];
                ldsm4(bh, sb + PJ_WH + jrow * 128 + (bcol ^ ((jrow & 7) << 4)));
                mma16816(acc[nt2*2],   ah, bh);
                mma16816(acc[nt2*2+1], ah, bh + 2);
                mma16816(acc[nt2*2],   al, bh);
                mma16816(acc[nt2*2+1], al, bh + 2);
                if (isQK) {
                    uint32_t bl[4];
                    ldsm4(bl, sb + PJ_WL + jrow * 128 + (bcol ^ ((jrow & 7) << 4)));
                    mma16816(acc[nt2*2],   ah, bl);
                    mma16816(acc[nt2*2+1], ah, bl + 2);
                }
            }
        }
    }

    // ---- epilogue
    const int rA = wn * 16 + (lane >> 2), rB = rA + 8;
    if (isQK) {
#pragma unroll
        for (int t = 0; t < 4; t++) {
            int j = wj * 32 + (t >> 1) * 16 + (t & 1) * 8 + 2 * (lane & 3);
            bool isQ = j < 32;
            int qc = isQ ? j : j - 32;
            char* tb = (char*)((isQ ? g_qt : g_kt) + ((size_t)(b * 64 + blockIdx.x)) * 4096);
#pragma unroll
            for (int rr = 0; rr < 2; rr++) {
                int r = rr ? rB : rA;
                float v0 = acc[t][rr * 2], v1 = acc[t][rr * 2 + 1];
                __half h0 = __float2half_rn(v0), h1 = __float2half_rn(v1);
                __half l0 = __float2half_rn(v0 - __half2float(h0));
                __half l1 = __float2half_rn(v1 - __half2float(h1));
                uint32_t hp = (uint32_t)*(uint16_t*)&h0 | ((uint32_t)*(uint16_t*)&h1 << 16);
                uint32_t lp = (uint32_t)*(uint16_t*)&l0 | ((uint32_t)*(uint16_t*)&l1 << 16);
                *(uint32_t*)(tb + r * 128 + ((qc * 2)      ^ ((r & 7) << 4))) = hp;
                *(uint32_t*)(tb + r * 128 + ((64 + qc * 2) ^ ((r & 7) << 4))) = lp;
            }
        }
    } else {
        __syncthreads();   // last-chunk ldsm reads of PJ_XH done
        __half* st = (__half*)(smc + PJ_XH);   // stage [64j][72n pitch]
#pragma unroll
        for (int t = 0; t < 4; t++) {
            int j = wj * 32 + (t >> 1) * 16 + (t & 1) * 8 + 2 * (lane & 3);
            st[j * 72 + rA]       = __float2half_rn(acc[t][0]);
            st[(j + 1) * 72 + rA] = __float2half_rn(acc[t][1]);
            st[j * 72 + rB]       = __float2half_rn(acc[t][2]);
            st[(j + 1) * 72 + rB] = __float2half_rn(acc[t][3]);
        }
        __syncthreads();
        char* tb = (char*)(g_vt + ((size_t)(b * 64 + blockIdx.x)) * 16384);
        int jl = tid >> 2, n8 = tid & 3;
        int c = jt * 64 + jl;
#pragma unroll
        for (int hh = 0; hh < 2; hh++) {
            int nl = n8 * 16 + hh * 8;
            uint4 v = *(uint4*)(smc + PJ_XH + (jl * 72 + nl) * 2);
            *(uint4*)(tb + c * 128 + ((nl * 2) ^ ((c & 7) << 4))) = v;
        }
    }
}

// ---------------------------------------------------------------------------
// Kernel 2: HMMA flash attention (R8 structure, split K/V barriers).
// ---------------------------------------------------------------------------
#define OFF_P   0          /* 32 x 144B = 4608 (also Q staging: 4096) */
#define OFF_RDT 4608       /* 16384 */
#define OFF_K   20992      /* 2 x 8192 */
#define OFF_V   37376      /* 2 x 32768 */
#define OFF_MX  102912     /* 4 x 32 f32 */
#define OFF_LS  103424     /* 4 x 32 f32 */
#define OFF_BAR 103936     /* barK0 barK1 barV0 barV1 */
#define SMEM_SZ 104064

__global__ __launch_bounds__(256, 2) void attn_kernel(
    const float* __restrict__ x, const float* __restrict__ gamma,
    const float* __restrict__ beta, const float* __restrict__ mean,
    const float* __restrict__ var, float* __restrict__ out)
{
    extern __shared__ char smc[];
    float* rdt = (float*)(smc + OFF_RDT);
    float* mx  = (float*)(smc + OFF_MX);
    float* ls  = (float*)(smc + OFF_LS);
    const uint32_t sb = smem_u32(smc);
    const uint32_t barK0 = sb + OFF_BAR, barK1 = sb + OFF_BAR + 8;
    const uint32_t barV0 = sb + OFF_BAR + 16, barV1 = sb + OFF_BAR + 24;
    const uint32_t sbP = sb + OFF_P;
    const int tid = threadIdx.x, w = tid >> 5, lane = tid & 31;
    const int wm = w & 1, wc = w >> 1;
    const int b = blockIdx.y, qt = blockIdx.x, qb = qt * 32;

    for (int i = tid; i < 4096; i += 256) {
        int dy = i >> 6, dx = i & 63;
        rdt[i] = 1.0f / (sqrtf((float)(dy * dy + dx * dx)) + 1.0f);
    }
    if (tid == 0) {
        MBAR_INIT(barK0, 1); MBAR_INIT(barK1, 1);
        MBAR_INIT(barV0, 1); MBAR_INIT(barV1, 1);
    }
    {   // Q staging: 32 rows x 128B slice of the 64-row swizzled q-tile
        const char* qsrc = (const char*)(g_qt + ((size_t)(b * 64 + (qt >> 1))) * 4096)
                         + (size_t)(qt & 1) * 32 * 128;
        ((uint4*)smc)[tid] = ((const uint4*)qsrc)[tid];
    }
    __syncthreads();

    uint32_t qf[2][2][4];
#pragma unroll
    for (int hl = 0; hl < 2; hl++)
#pragma unroll
        for (int kk = 0; kk < 2; kk++) {
            int row = wm * 16 + (lane & 7) + ((lane & 8) ? 8 : 0);
            int colb = hl * 64 + kk * 32 + ((lane & 16) ? 16 : 0);
            ldsm4(qf[hl][kk], sbP + row * 128 + (colb ^ ((row & 7) << 4)));
        }

    const __half* kt = g_kt + (size_t)b * 64 * 4096;
    const __half* vt = g_vt + (size_t)b * 64 * 16384;

    if (tid == 0) {
        MBAR_EXPECT_TX(barK0, 8192);  bulk_g2s(sb + OFF_K, kt, 8192, barK0);
        MBAR_EXPECT_TX(barV0, 32768); bulk_g2s(sb + OFF_V, vt, 32768, barV0);
    }
    __syncthreads();   // qf loads done before any P writes

    float y[8][4];
#pragma unroll
    for (int i = 0; i < 8; i++)
#pragma unroll
        for (int j = 0; j < 4; j++) y[i][j] = 0.f;
    float mA = -1e30f, mB = -1e30f, lA = 0.f, lB = 0.f;
    const int rxA = wm * 16 + (lane >> 2), rxB = rxA + 8;
    const int c0 = 2 * (lane & 3);
    const int rxAi = (qt & 1) * 32 + rxA, rxBi = rxAi + 8;
    const int ry = qt >> 1;

    for (int t = 0; t < 64; t++) {
        MBAR_WAIT(((t & 1) ? barK1 : barK0), (t >> 1) & 1);
        const uint32_t bK = sb + OFF_K + (t & 1) * 8192;
        const uint32_t bV = sb + OFF_V + (t & 1) * 32768;

        float s[2][4];
#pragma unroll
        for (int f = 0; f < 2; f++)
#pragma unroll
            for (int j = 0; j < 4; j++) s[f][j] = 0.f;
        {
            int krow = wc * 16 + (lane & 7) + ((lane & 16) ? 8 : 0);
#pragma unroll
            for (int kk = 0; kk < 2; kk++) {
                int colb = kk * 32 + ((lane & 8) ? 16 : 0);
                uint32_t bh[4], bl[4];
                ldsm4(bh, bK + krow * 128 + (colb ^ ((krow & 7) << 4)));
                ldsm4(bl, bK + krow * 128 + ((colb + 64) ^ ((krow & 7) << 4)));
                mma16816(s[0], qf[0][kk], bh);
                mma16816(s[1], qf[0][kk], bh + 2);
                mma16816(s[0], qf[1][kk], bh);
                mma16816(s[1], qf[1][kk], bh + 2);
                mma16816(s[0], qf[0][kk], bl);
                mma16816(s[1], qf[0][kk], bl + 2);
            }
        }

        const float* rdtp = rdt + ((ry > t) ? (ry - t) : (t - ry)) * 64;
        float tmA = -1e30f, tmB = -1e30f;
#pragma unroll
        for (int j = 0; j < 2; j++) {
            int c = wc * 16 + j * 8 + c0;
            int d0 = rxAi - c;     d0 = d0 < 0 ? -d0 : d0;
            int d1 = rxAi - c - 1; d1 = d1 < 0 ? -d1 : d1;
            int d2 = rxBi - c;     d2 = d2 < 0 ? -d2 : d2;
            int d3 = rxBi - c - 1; d3 = d3 < 0 ? -d3 : d3;
            s[j][0] *= rdtp[d0];
            s[j][1] *= rdtp[d1];
            s[j][2] *= rdtp[d2];
            s[j][3] *= rdtp[d3];
            tmA = fmaxf(tmA, fmaxf(s[j][0], s[j][1]));
            tmB = fmaxf(tmB, fmaxf(s[j][2], s[j][3]));
        }
        tmA = fmaxf(tmA, __shfl_xor_sync(0xffffffffu, tmA, 1));
        tmA = fmaxf(tmA, __shfl_xor_sync(0xffffffffu, tmA, 2));
        tmB = fmaxf(tmB, __shfl_xor_sync(0xffffffffu, tmB, 1));
        tmB = fmaxf(tmB, __shfl_xor_sync(0xffffffffu, tmB, 2));
        if ((lane & 3) == 0) {
            mx[wc * 32 + rxA] = tmA;
            mx[wc * 32 + rxB] = tmB;
        }
        __syncthreads();   // stats visible; GEMM2(t-1) reads done

        if (tid == 0 && t + 1 < 64) {
            uint32_t st = (t + 1) & 1;
            MBAR_EXPECT_TX((st ? barK1 : barK0), 8192);
            bulk_g2s(sb + OFF_K + st * 8192,  kt + (size_t)(t + 1) * 4096,  8192,  st ? barK1 : barK0);
            MBAR_EXPECT_TX((st ? barV1 : barV0), 32768);
            bulk_g2s(sb + OFF_V + st * 32768, vt + (size_t)(t + 1) * 16384, 32768, st ? barV1 : barV0);
        }

        float gmA = fmaxf(fmaxf(mx[rxA], mx[32 + rxA]), fmaxf(mx[64 + rxA], mx[96 + rxA]));
        float gmB = fmaxf(fmaxf(mx[rxB], mx[32 + rxB]), fmaxf(mx[64 + rxB], mx[96 + rxB]));
        float mnA = fmaxf(mA, gmA), mnB = fmaxf(mB, gmB);
        float scA = __expf(mA - mnA), scB = __expf(mB - mnB);
        mA = mnA; mB = mnB;
        if (!__all_sync(0xffffffffu, (scA == 1.f) && (scB == 1.f))) {
            lA *= scA; lB *= scB;
#pragma unroll
            for (int nt = 0; nt < 8; nt++) {
                y[nt][0] *= scA; y[nt][1] *= scA;
                y[nt][2] *= scB; y[nt][3] *= scB;
            }
        }
        float sumA = 0.f, sumB = 0.f;
#pragma unroll
        for (int j = 0; j < 2; j++) {
            float p0 = __expf(s[j][0] - mnA), p1 = __expf(s[j][1] - mnA);
            float p2 = __expf(s[j][2] - mnB), p3 = __expf(s[j][3] - mnB);
            sumA += p0 + p1; sumB += p2 + p3;
            int c = wc * 16 + j * 8 + c0;
            *(uint32_t*)(smc + OFF_P + (rxA * 72 + c) * 2) = pk(p0, p1);
            *(uint32_t*)(smc + OFF_P + (rxB * 72 + c) * 2) = pk(p2, p3);
        }
        sumA += __shfl_xor_sync(0xffffffffu, sumA, 1);
        sumA += __shfl_xor_sync(0xffffffffu, sumA, 2);
        sumB += __shfl_xor_sync(0xffffffffu, sumB, 1);
        sumB += __shfl_xor_sync(0xffffffffu, sumB, 2);
        lA += sumA; lB += sumB;
        __syncthreads();            // P visible

        MBAR_WAIT(((t & 1) ? barV1 : barV0), (t >> 1) & 1);
#pragma unroll
        for (int kk = 0; kk < 4; kk++) {
            uint32_t pa[4];
            int prow = wm * 16 + (lane & 7) + ((lane & 8) ? 8 : 0);
            int pcol = kk * 16 + ((lane & 16) ? 8 : 0);
            ldsm4(pa, sbP + (prow * 72 + pcol) * 2);
#pragma unroll
            for (int np = 0; np < 4; np++) {
                int vrow = wc * 64 + np * 16 + (lane & 7) + ((lane & 16) ? 8 : 0);
                int colb = kk * 32 + ((lane & 8) ? 16 : 0);
                uint32_t bv[4];
                ldsm4(bv, bV + vrow * 128 + (colb ^ ((vrow & 7) << 4)));
                mma16816(y[np*2],   pa, bv);
                mma16816(y[np*2+1], pa, bv + 2);
            }
        }
    }

    if ((lane & 3) == 0) {
        ls[wc * 32 + rxA] = lA;
        ls[wc * 32 + rxB] = lB;
    }
    __syncthreads();
    const float rlA = 1.f / (ls[rxA] + ls[32 + rxA] + ls[64 + rxA] + ls[96 + rxA]);
    const float rlB = 1.f / (ls[rxB] + ls[32 + rxB] + ls[64 + rxB] + ls[96 + rxB]);

    float* Ys = (float*)smc;   // [32][260] f32
#pragma unroll
    for (int nt = 0; nt < 8; nt++) {
        int c = wc * 64 + (nt >> 1) * 16 + (nt & 1) * 8 + c0;
        Ys[rxA * 260 + c]     = y[nt][0] * rlA;
        Ys[rxA * 260 + c + 1] = y[nt][1] * rlA;
        Ys[rxB * 260 + c]     = y[nt][2] * rlB;
        Ys[rxB * 260 + c + 1] = y[nt][3] * rlB;
    }
    __syncthreads();
    const int n = tid & 31, cg = tid >> 5;
#pragma unroll 4
    for (int it = 0; it < 32; it++) {
        int c = it * 8 + cg;
        float inv = gamma[c] * rsqrtf(var[c] + 1e-5f);
        float add = fmaf(-mean[c], inv, beta[c]);
        size_t idx = ((size_t)b * C_ + c) * N_ + qb + n;
        float yv = Ys[n * 260 + c];
        out[idx] = fmaxf(fmaf(yv, inv, add), 0.f) + x[idx];
    }
}

// ---------------------------------------------------------------------------
extern "C" void kernel_launch(void* const* d_in, const int* in_sizes, int n_in,
                              void* d_out, int out_size)
{
    (void)in_sizes; (void)n_in; (void)out_size;
    const float* x     = (const float*)d_in[0];
    const float* wv    = (const float*)d_in[1];
    const float* wq    = (const float*)d_in[2];
    const float* wk    = (const float*)d_in[3];
    const float* gamma = (const float*)d_in[4];
    const float* beta  = (const float*)d_in[5];
    const float* mean  = (const float*)d_in[6];
    const float* var   = (const float*)d_in[7];
    float* out = (float*)d_out;

    cudaFuncSetAttribute(proj_kernel, cudaFuncAttributeMaxDynamicSharedMemorySize, PJ_SZ);
    proj_kernel<<<dim3(64, 5, B_), 256, PJ_SZ>>>(x, wv, wq, wk);
    cudaFuncSetAttribute(attn_kernel, cudaFuncAttributeMaxDynamicSharedMemorySize, SMEM_SZ);
    attn_kernel<<<dim3(128, B_), 256, SMEM_SZ>>>(x, gamma, beta, mean, var, out);
}

// round 11
// speedup vs baseline: 1.6366x; 1.1315x over previous
#include <cuda_runtime.h>
#include <cuda_fp16.h>
#include <stdint.h>

#define B_ 4
#define C_ 256
#define N_ 4096

// ---------------- device scratch (swizzled tile layouts, attn-ready) --------
__device__ __align__(256) __half g_qt [(size_t)B_ * 64 * 4096]; // 8KB q-tiles [r][qh32|ql32] sw128
__device__ __align__(256) __half g_kt [(size_t)B_ * 64 * 4096]; // 8KB k-tiles
__device__ __align__(256) __half g_vt [(size_t)B_ * 64 * 16384];// 32KB V^T tiles [c][n] sw128

// ---------------- asm helpers ----------------
__device__ __forceinline__ uint32_t smem_u32(const void* p) {
    uint32_t a;
    asm("{ .reg .u64 t; cvta.to.shared.u64 t, %1; cvt.u32.u64 %0, t; }" : "=r"(a) : "l"(p));
    return a;
}
__device__ __forceinline__ void ldsm4(uint32_t* r, uint32_t a) {
    asm volatile("ldmatrix.sync.aligned.m8n8.x4.shared.b16 {%0,%1,%2,%3}, [%4];"
        : "=r"(r[0]), "=r"(r[1]), "=r"(r[2]), "=r"(r[3]) : "r"(a));
}
__device__ __forceinline__ void mma16816(float* c, const uint32_t* a, const uint32_t* b) {
    asm volatile("mma.sync.aligned.m16n8k16.row.col.f32.f16.f16.f32 "
        "{%0,%1,%2,%3}, {%4,%5,%6,%7}, {%8,%9}, {%0,%1,%2,%3};"
        : "+f"(c[0]), "+f"(c[1]), "+f"(c[2]), "+f"(c[3])
        : "r"(a[0]), "r"(a[1]), "r"(a[2]), "r"(a[3]), "r"(b[0]), "r"(b[1]));
}
__device__ __forceinline__ uint32_t pk(float lo, float hi) {
    uint32_t r;
    asm("cvt.rn.f16x2.f32 %0, %1, %2;" : "=r"(r) : "f"(hi), "f"(lo));
    return r;
}
#define MBAR_INIT(m, c) \
    asm volatile("mbarrier.init.shared.b64 [%0], %1;" :: "r"((uint32_t)(m)), "r"((uint32_t)(c)) : "memory")
#define MBAR_EXPECT_TX(m, b) \
    asm volatile("mbarrier.arrive.expect_tx.shared.b64 _, [%0], %1;" :: "r"((uint32_t)(m)), "r"((uint32_t)(b)) : "memory")
#define MBAR_WAIT(m, ph) do { \
    uint32_t _m = (uint32_t)(m), _p = (uint32_t)(ph), _d; \
    asm volatile("{\n\t.reg .pred p;\n\t" \
        "mbarrier.try_wait.parity.acquire.cta.shared::cta.b64 p, [%1], %2;\n\tselp.b32 %0,1,0,p;\n\t}" \
        : "=r"(_d) : "r"(_m), "r"(_p) : "memory"); \
    if (!_d) { asm volatile("{\n\t.reg .pred P1;\n\tWL_%=:\n\t" \
        "mbarrier.try_wait.parity.acquire.cta.shared::cta.b64 P1, [%0], %1, 0x989680;\n\t" \
        "@P1 bra.uni WD_%=;\n\tbra.uni WL_%=;\n\tWD_%=:\n\t}" :: "r"(_m), "r"(_p) : "memory"); } \
} while (0)
__device__ __forceinline__ void bulk_g2s(uint32_t dst, const void* src, uint32_t bytes, uint32_t mbar) {
    asm volatile("cp.async.bulk.shared::cluster.global.mbarrier::complete_tx::bytes [%0], [%1], %2, [%3];"
        :: "r"(dst), "l"(__cvta_generic_to_global(src)), "r"(bytes), "r"(mbar) : "memory");
}
#define NBAR_SYNC(id, cnt)   asm volatile("bar.sync %0, %1;"   :: "r"(id), "r"(cnt) : "memory")
#define NBAR_ARRIVE(id, cnt) asm volatile("bar.arrive %0, %1;" :: "r"(id), "r"(cnt) : "memory")

// ---------------------------------------------------------------------------
// Kernel 1: HMMA projection (unchanged from R9 — passed, rel 5.7e-5).
// ---------------------------------------------------------------------------
#define PJ_WH  0
#define PJ_WL  8192
#define PJ_X32 16384
#define PJ_XH  33792
#define PJ_XL  43008
#define PJ_SZ  52224

__global__ __launch_bounds__(256, 2) void proj_kernel(
    const float* __restrict__ x, const float* __restrict__ wv,
    const float* __restrict__ wq, const float* __restrict__ wk)
{
    extern __shared__ char smc[];
    float* xs32 = (float*)(smc + PJ_X32);
    const uint32_t sb = smem_u32(smc);
    const int tid = threadIdx.x, w = tid >> 5, lane = tid & 31;
    const int wn = w & 3, wj = w >> 2;
    const int b = blockIdx.z, n0 = blockIdx.x * 64, jt = blockIdx.y;
    const bool isQK = (jt == 4);

    float acc[4][4];
#pragma unroll
    for (int i = 0; i < 4; i++)
#pragma unroll
        for (int j = 0; j < 4; j++) acc[i][j] = 0.f;

    for (int c0 = 0; c0 < 256; c0 += 64) {
        __syncthreads();
#pragma unroll
        for (int it = 0; it < 4; it++) {
            int f4 = tid + it * 256;
            int jl = f4 >> 4, c4 = f4 & 15;
            const float* src;
            if (!isQK) src = wv + (size_t)(jt * 64 + jl) * 256 + c0 + c4 * 4;
            else src = ((jl < 32) ? (wq + (size_t)jl * 256) : (wk + (size_t)(jl - 32) * 256)) + c0 + c4 * 4;
            float4 v = *(const float4*)src;
            __half h[4];
            h[0] = __float2half_rn(v.x); h[1] = __float2half_rn(v.y);
            h[2] = __float2half_rn(v.z); h[3] = __float2half_rn(v.w);
            *(uint2*)(smc + PJ_WH + jl * 128 + ((c4 * 8) ^ ((jl & 7) << 4))) = *(uint2*)h;
            if (isQK) {
                __half l[4];
                l[0] = __float2half_rn(v.x - __half2float(h[0]));
                l[1] = __float2half_rn(v.y - __half2float(h[1]));
                l[2] = __float2half_rn(v.z - __half2float(h[2]));
                l[3] = __float2half_rn(v.w - __half2float(h[3]));
                *(uint2*)(smc + PJ_WL + jl * 128 + ((c4 * 8) ^ ((jl & 7) << 4))) = *(uint2*)l;
            }
        }
#pragma unroll
        for (int it = 0; it < 4; it++) {
            int f4 = tid + it * 256;
            int cl = f4 >> 4, n4 = f4 & 15;
            float4 v = *(const float4*)(x + (size_t)(b * 256 + c0 + cl) * 4096 + n0 + n4 * 4);
            *(float4*)(xs32 + cl * 68 + n4 * 4) = v;
        }
        __syncthreads();
        {
            int n = tid & 63, cq = tid >> 6;
#pragma unroll
            for (int i = 0; i < 4; i++) {
                int c = cq * 16 + i * 4;
                __half h[4], l[4];
#pragma unroll
                for (int k2 = 0; k2 < 4; k2++) {
                    float f = xs32[(c + k2) * 68 + n];
                    h[k2] = __float2half_rn(f);
                    l[k2] = __float2half_rn(f - __half2float(h[k2]));
                }
                *(uint2*)(smc + PJ_XH + n * 144 + c * 2) = *(uint2*)h;
                *(uint2*)(smc + PJ_XL + n * 144 + c * 2) = *(uint2*)l;
            }
        }
        __syncthreads();
#pragma unroll
        for (int kk = 0; kk < 4; kk++) {
            uint32_t ah[4], al[4];
            int arow = wn * 16 + (lane & 7) + ((lane & 8) ? 8 : 0);
            int aoff = arow * 144 + kk * 32 + ((lane & 16) ? 16 : 0);
            ldsm4(ah, sb + PJ_XH + aoff);
            ldsm4(al, sb + PJ_XL + aoff);
            int jr0 = wj * 32 + (lane & 7) + ((lane & 16) ? 8 : 0);
            int bcol = kk * 32 + ((lane & 8) ? 16 : 0);
#pragma unroll
            for (int nt2 = 0; nt2 < 2; nt2++) {
                int jrow = jr0 + nt2 * 16;
                uint32_t bh[4];
                ldsm4(bh, sb + PJ_WH + jrow * 128 + (bcol ^ ((jrow & 7) << 4)));
                mma16816(acc[nt2*2],   ah, bh);
                mma16816(acc[nt2*2+1], ah, bh + 2);
                mma16816(acc[nt2*2],   al, bh);
                mma16816(acc[nt2*2+1], al, bh + 2);
                if (isQK) {
                    uint32_t bl[4];
                    ldsm4(bl, sb + PJ_WL + jrow * 128 + (bcol ^ ((jrow & 7) << 4)));
                    mma16816(acc[nt2*2],   ah, bl);
                    mma16816(acc[nt2*2+1], ah, bl + 2);
                }
            }
        }
    }

    const int rA = wn * 16 + (lane >> 2), rB = rA + 8;
    if (isQK) {
#pragma unroll
        for (int t = 0; t < 4; t++) {
            int j = wj * 32 + (t >> 1) * 16 + (t & 1) * 8 + 2 * (lane & 3);
            bool isQ = j < 32;
            int qc = isQ ? j : j - 32;
            char* tb = (char*)((isQ ? g_qt : g_kt) + ((size_t)(b * 64 + blockIdx.x)) * 4096);
#pragma unroll
            for (int rr = 0; rr < 2; rr++) {
                int r = rr ? rB : rA;
                float v0 = acc[t][rr * 2], v1 = acc[t][rr * 2 + 1];
                __half h0 = __float2half_rn(v0), h1 = __float2half_rn(v1);
                __half l0 = __float2half_rn(v0 - __half2float(h0));
                __half l1 = __float2half_rn(v1 - __half2float(h1));
                uint32_t hp = (uint32_t)*(uint16_t*)&h0 | ((uint32_t)*(uint16_t*)&h1 << 16);
                uint32_t lp = (uint32_t)*(uint16_t*)&l0 | ((uint32_t)*(uint16_t*)&l1 << 16);
                *(uint32_t*)(tb + r * 128 + ((qc * 2)      ^ ((r & 7) << 4))) = hp;
                *(uint32_t*)(tb + r * 128 + ((64 + qc * 2) ^ ((r & 7) << 4))) = lp;
            }
        }
    } else {
        __syncthreads();
        __half* st = (__half*)(smc + PJ_XH);
#pragma unroll
        for (int t = 0; t < 4; t++) {
            int j = wj * 32 + (t >> 1) * 16 + (t & 1) * 8 + 2 * (lane & 3);
            st[j * 72 + rA]       = __float2half_rn(acc[t][0]);
            st[(j + 1) * 72 + rA] = __float2half_rn(acc[t][1]);
            st[j * 72 + rB]       = __float2half_rn(acc[t][2]);
            st[(j + 1) * 72 + rB] = __float2half_rn(acc[t][3]);
        }
        __syncthreads();
        char* tb = (char*)(g_vt + ((size_t)(b * 64 + blockIdx.x)) * 16384);
        int jl = tid >> 2, n8 = tid & 3;
        int c = jt * 64 + jl;
#pragma unroll
        for (int hh = 0; hh < 2; hh++) {
            int nl = n8 * 16 + hh * 8;
            uint4 v = *(uint4*)(smc + PJ_XH + (jl * 72 + nl) * 2);
            *(uint4*)(tb + c * 128 + ((nl * 2) ^ ((c & 7) << 4))) = v;
        }
    }
}

// ---------------------------------------------------------------------------
// Kernel 2: warp-specialized HMMA flash attention (race-free protocol).
// G1 (w 0-3): GEMM1+softmax -> P/sc slots; K pipeline.
// G2 (w 4-7): rescale + GEMM2; V pipeline.  1 tile of skew.
// Named bars: 1 G1-internal(128), 4 G2-internal(128),
//   ready[p] = 2+p (G1 arrive / G2 sync, 256), free[p] = 8+p (G2 arrive / G1 sync, 256),
//   6,7 epilogue rendezvous (256).
// ---------------------------------------------------------------------------
#define OFF_P   0          /* 2 x 4608 (slot0 head doubles as 4KB Q staging) */
#define OFF_SC  9216       /* 2 x 32 f32 */
#define OFF_MX  9472       /* 2 x 2 x 32 f32 */
#define OFF_LS  9984       /* 2 x 32 f32 */
#define OFF_RDT 10240      /* 16384 */
#define OFF_K   26624      /* 2 x 8192 */
#define OFF_V   43008      /* 2 x 32768 */
#define OFF_BAR 108544
#define SMEM_SZ 108608

__global__ __launch_bounds__(256, 2) void attn_kernel(
    const float* __restrict__ x, const float* __restrict__ gamma,
    const float* __restrict__ beta, const float* __restrict__ mean,
    const float* __restrict__ var, float* __restrict__ out)
{
    extern __shared__ char smc[];
    float* rdt = (float*)(smc + OFF_RDT);
    float* ls  = (float*)(smc + OFF_LS);
    const uint32_t sb = smem_u32(smc);
    const uint32_t barK0 = sb + OFF_BAR, barK1 = sb + OFF_BAR + 8;
    const uint32_t barV0 = sb + OFF_BAR + 16, barV1 = sb + OFF_BAR + 24;
    const int tid = threadIdx.x, w = tid >> 5, lane = tid & 31;
    const int b = blockIdx.y, qt = blockIdx.x, qb = qt * 32;

    for (int i = tid; i < 4096; i += 256) {
        int dy = i >> 6, dx = i & 63;
        rdt[i] = 1.0f / (sqrtf((float)(dy * dy + dx * dx)) + 1.0f);
    }
    if (tid == 0) {
        MBAR_INIT(barK0, 1); MBAR_INIT(barK1, 1);
        MBAR_INIT(barV0, 1); MBAR_INIT(barV1, 1);
    }
    {   // Q staging into P slot0 head (4KB); consumed into regs before t=0 writes
        const char* qsrc = (const char*)(g_qt + ((size_t)(b * 64 + (qt >> 1))) * 4096)
                         + (size_t)(qt & 1) * 32 * 128;
        ((uint4*)smc)[tid] = ((const uint4*)qsrc)[tid];
    }
    __syncthreads();

    const __half* kt = g_kt + (size_t)b * 64 * 4096;
    const __half* vt = g_vt + (size_t)b * 64 * 16384;
    if (tid == 0) {   // prologue: K(0),K(1),V(0),V(1)
        MBAR_EXPECT_TX(barK0, 8192);  bulk_g2s(sb + OFF_K, kt, 8192, barK0);
        MBAR_EXPECT_TX(barK1, 8192);  bulk_g2s(sb + OFF_K + 8192, kt + 4096, 8192, barK1);
        MBAR_EXPECT_TX(barV0, 32768); bulk_g2s(sb + OFF_V, vt, 32768, barV0);
        MBAR_EXPECT_TX(barV1, 32768); bulk_g2s(sb + OFF_V + 32768, vt + 16384, 32768, barV1);
    }

    if (w < 4) {
        // ================= G1: GEMM1 + softmax =================
        const int wm = w & 1, wc = w >> 1;
        const int rxA = wm * 16 + (lane >> 2), rxB = rxA + 8;
        const int c0 = 2 * (lane & 3);
        const int rxAi = (qt & 1) * 32 + rxA, rxBi = rxAi + 8;
        const int ry = qt >> 1;

        uint32_t qf[2][2][4];
#pragma unroll
        for (int hl = 0; hl < 2; hl++)
#pragma unroll
            for (int kk = 0; kk < 2; kk++) {
                int row = wm * 16 + (lane & 7) + ((lane & 8) ? 8 : 0);
                int colb = hl * 64 + kk * 32 + ((lane & 16) ? 16 : 0);
                ldsm4(qf[hl][kk], sb + row * 128 + (colb ^ ((row & 7) << 4)));
            }
        NBAR_SYNC(1, 128);   // all G1 qf reads done before P slot0 writes at t=0

        float mA = -1e30f, mB = -1e30f, lA = 0.f, lB = 0.f;

        for (int t = 0; t < 64; t++) {
            MBAR_WAIT(((t & 1) ? barK1 : barK0), (t >> 1) & 1);
            const uint32_t bK = sb + OFF_K + (t & 1) * 8192;

            float s[4][4];
#pragma unroll
            for (int i = 0; i < 4; i++)
#pragma unroll
                for (int j = 0; j < 4; j++) s[i][j] = 0.f;
#pragma unroll
            for (int kk = 0; kk < 2; kk++) {
                int colb = kk * 32 + ((lane & 8) ? 16 : 0);
                int kr0 = wc * 32 + (lane & 7) + ((lane & 16) ? 8 : 0);
                uint32_t bh0[4], bh1[4], bl0[4], bl1[4];
                ldsm4(bh0, bK + kr0 * 128 + (colb ^ ((kr0 & 7) << 4)));
                ldsm4(bl0, bK + kr0 * 128 + ((colb + 64) ^ ((kr0 & 7) << 4)));
                int kr1 = kr0 + 16;
                ldsm4(bh1, bK + kr1 * 128 + (colb ^ ((kr1 & 7) << 4)));
                ldsm4(bl1, bK + kr1 * 128 + ((colb + 64) ^ ((kr1 & 7) << 4)));
                mma16816(s[0], qf[0][kk], bh0);
                mma16816(s[1], qf[0][kk], bh0 + 2);
                mma16816(s[2], qf[0][kk], bh1);
                mma16816(s[3], qf[0][kk], bh1 + 2);
                mma16816(s[0], qf[1][kk], bh0);
                mma16816(s[1], qf[1][kk], bh0 + 2);
                mma16816(s[2], qf[1][kk], bh1);
                mma16816(s[3], qf[1][kk], bh1 + 2);
                mma16816(s[0], qf[0][kk], bl0);
                mma16816(s[1], qf[0][kk], bl0 + 2);
                mma16816(s[2], qf[0][kk], bl1);
                mma16816(s[3], qf[0][kk], bl1 + 2);
            }

            const float* rdtp = rdt + ((ry > t) ? (ry - t) : (t - ry)) * 64;
            float tmA = -1e30f, tmB = -1e30f;
#pragma unroll
            for (int idx = 0; idx < 4; idx++) {
                int c = wc * 32 + (idx >> 1) * 16 + (idx & 1) * 8 + c0;
                int d0 = rxAi - c;     d0 = d0 < 0 ? -d0 : d0;
                int d1 = rxAi - c - 1; d1 = d1 < 0 ? -d1 : d1;
                int d2 = rxBi - c;     d2 = d2 < 0 ? -d2 : d2;
                int d3 = rxBi - c - 1; d3 = d3 < 0 ? -d3 : d3;
                s[idx][0] *= rdtp[d0];
                s[idx][1] *= rdtp[d1];
                s[idx][2] *= rdtp[d2];
                s[idx][3] *= rdtp[d3];
                tmA = fmaxf(tmA, fmaxf(s[idx][0], s[idx][1]));
                tmB = fmaxf(tmB, fmaxf(s[idx][2], s[idx][3]));
            }
            tmA = fmaxf(tmA, __shfl_xor_sync(0xffffffffu, tmA, 1));
            tmA = fmaxf(tmA, __shfl_xor_sync(0xffffffffu, tmA, 2));
            tmB = fmaxf(tmB, __shfl_xor_sync(0xffffffffu, tmB, 1));
            tmB = fmaxf(tmB, __shfl_xor_sync(0xffffffffu, tmB, 2));
            float* mxs = (float*)(smc + OFF_MX + (t & 1) * 256);
            if ((lane & 3) == 0) {
                mxs[wc * 32 + rxA] = tmA;
                mxs[wc * 32 + rxB] = tmB;
            }
            NBAR_SYNC(1, 128);
            if (tid == 0 && t + 2 < 64) {
                uint32_t bk = (t & 1) ? barK1 : barK0;
                MBAR_EXPECT_TX(bk, 8192);
                bulk_g2s(sb + OFF_K + (t & 1) * 8192, kt + (size_t)(t + 2) * 4096, 8192, bk);
            }
            float gmA = fmaxf(mxs[rxA], mxs[32 + rxA]);
            float gmB = fmaxf(mxs[rxB], mxs[32 + rxB]);
            float mnA = fmaxf(mA, gmA), mnB = fmaxf(mB, gmB);
            float scA = __expf(mA - mnA), scB = __expf(mB - mnB);
            mA = mnA; mB = mnB;

            float sumA = 0.f, sumB = 0.f;
            uint32_t pp[4][2];
#pragma unroll
            for (int idx = 0; idx < 4; idx++) {
                float p0 = __expf(s[idx][0] - mnA), p1 = __expf(s[idx][1] - mnA);
                float p2 = __expf(s[idx][2] - mnB), p3 = __expf(s[idx][3] - mnB);
                sumA += p0 + p1; sumB += p2 + p3;
                pp[idx][0] = pk(p0, p1);
                pp[idx][1] = pk(p2, p3);
            }
            sumA += __shfl_xor_sync(0xffffffffu, sumA, 1);
            sumA += __shfl_xor_sync(0xffffffffu, sumA, 2);
            sumB += __shfl_xor_sync(0xffffffffu, sumB, 1);
            sumB += __shfl_xor_sync(0xffffffffu, sumB, 2);
            lA = lA * scA + sumA;
            lB = lB * scB + sumB;

            if (t >= 2) NBAR_SYNC(8 + (t & 1), 256);   // slot free (G2 done t-2)
            char* Pb = smc + OFF_P + (t & 1) * 4608;
#pragma unroll
            for (int idx = 0; idx < 4; idx++) {
                int c = wc * 32 + (idx >> 1) * 16 + (idx & 1) * 8 + c0;
                *(uint32_t*)(Pb + (rxA * 72 + c) * 2) = pp[idx][0];
                *(uint32_t*)(Pb + (rxB * 72 + c) * 2) = pp[idx][1];
            }
            if (wc == 0 && (lane & 3) == 0) {
                float* scb = (float*)(smc + OFF_SC + (t & 1) * 128);
                scb[rxA] = scA;
                scb[rxB] = scB;
            }
            NBAR_ARRIVE(2 + (t & 1), 256);             // P(t) ready
        }
        if ((lane & 3) == 0) {
            ls[wc * 32 + rxA] = lA;
            ls[wc * 32 + rxB] = lB;
        }
        NBAR_SYNC(6, 256);   // ls visible to G2
        NBAR_SYNC(7, 256);   // G2's Ys writes done
    } else {
        // ================= G2: rescale + GEMM2 =================
        const int wq2 = w - 4;
        const int c0 = 2 * (lane & 3);
        const int r0 = lane >> 2;

        float y[2][8][4];
#pragma unroll
        for (int bd = 0; bd < 2; bd++)
#pragma unroll
            for (int i = 0; i < 8; i++)
#pragma unroll
                for (int j = 0; j < 4; j++) y[bd][i][j] = 0.f;

        for (int t = 0; t < 64; t++) {
            NBAR_SYNC(2 + (t & 1), 256);      // P(t), sc(t) ready
            const float* scb = (const float*)(smc + OFF_SC + (t & 1) * 128);
            float s0 = scb[r0], s1 = scb[r0 + 8], s2 = scb[r0 + 16], s3 = scb[r0 + 24];
            bool nor = (s0 == 1.f) & (s1 == 1.f) & (s2 == 1.f) & (s3 == 1.f);
            if (!__all_sync(0xffffffffu, nor)) {
#pragma unroll
                for (int i = 0; i < 8; i++) {
                    y[0][i][0] *= s0; y[0][i][1] *= s0;
                    y[0][i][2] *= s1; y[0][i][3] *= s1;
                    y[1][i][0] *= s2; y[1][i][1] *= s2;
                    y[1][i][2] *= s3; y[1][i][3] *= s3;
                }
            }
            MBAR_WAIT(((t & 1) ? barV1 : barV0), (t >> 1) & 1);
            const uint32_t bV = sb + OFF_V + (t & 1) * 32768;
            const uint32_t Pb = sb + OFF_P + (t & 1) * 4608;
#pragma unroll
            for (int kk = 0; kk < 4; kk++) {
                uint32_t pa0[4], pa1[4];
                int pr = (lane & 7) + ((lane & 8) ? 8 : 0);
                int pc = kk * 16 + ((lane & 16) ? 8 : 0);
                ldsm4(pa0, Pb + (pr * 72 + pc) * 2);
                ldsm4(pa1, Pb + ((pr + 16) * 72 + pc) * 2);
                int colb = kk * 32 + ((lane & 8) ? 16 : 0);
#pragma unroll
                for (int np = 0; np < 4; np++) {
                    int vrow = wq2 * 64 + np * 16 + (lane & 7) + ((lane & 16) ? 8 : 0);
                    uint32_t bv[4];
                    ldsm4(bv, bV + vrow * 128 + (colb ^ ((vrow & 7) << 4)));
                    mma16816(y[0][np*2],   pa0, bv);
                    mma16816(y[0][np*2+1], pa0, bv + 2);
                    mma16816(y[1][np*2],   pa1, bv);
                    mma16816(y[1][np*2+1], pa1, bv + 2);
                }
            }
            NBAR_SYNC(4, 128);                // all G2 done with V(t)/P(t)
            if (tid == 128 && t + 2 < 64) {
                uint32_t bv2 = (t & 1) ? barV1 : barV0;
                MBAR_EXPECT_TX(bv2, 32768);
                bulk_g2s(sb + OFF_V + (t & 1) * 32768, vt + (size_t)(t + 2) * 16384, 32768, bv2);
            }
            if (t < 62) NBAR_ARRIVE(8 + (t & 1), 256);   // P slot free
        }

        NBAR_SYNC(6, 256);   // ls visible
        float rl[4];
#pragma unroll
        for (int q = 0; q < 4; q++) {
            int r = r0 + q * 8;
            rl[q] = 1.f / (ls[r] + ls[32 + r]);
        }
        NBAR_SYNC(4, 128);   // all G2 read ls before Ys overwrite
        float* Ys = (float*)smc;   // [32][260] f32 (overlaps P/sc/mx/ls/rdt — all dead)
#pragma unroll
        for (int bd = 0; bd < 2; bd++)
#pragma unroll
            for (int nt = 0; nt < 8; nt++) {
                int c = wq2 * 64 + (nt >> 1) * 16 + (nt & 1) * 8 + c0;
                int rA = bd * 16 + r0, rB = rA + 8;
                Ys[rA * 260 + c]     = y[bd][nt][0] * rl[bd * 2];
                Ys[rA * 260 + c + 1] = y[bd][nt][1] * rl[bd * 2];
                Ys[rB * 260 + c]     = y[bd][nt][2] * rl[bd * 2 + 1];
                Ys[rB * 260 + c + 1] = y[bd][nt][3] * rl[bd * 2 + 1];
            }
        NBAR_SYNC(7, 256);   // Ys published
    }

    // ---- common epilogue: BN + ReLU + residual (Ys visible after bar 7)
    float* Ys = (float*)smc;
    const int n = tid & 31, cg = tid >> 5;
#pragma unroll 4
    for (int it = 0; it < 32; it++) {
        int c = it * 8 + cg;
        float inv = gamma[c] * rsqrtf(var[c] + 1e-5f);
        float add = fmaf(-mean[c], inv, beta[c]);
        size_t idx = ((size_t)b * C_ + c) * N_ + qb + n;
        float yv = Ys[n * 260 + c];
        out[idx] = fmaxf(fmaf(yv, inv, add), 0.f) + x[idx];
    }
}

// ---------------------------------------------------------------------------
extern "C" void kernel_launch(void* const* d_in, const int* in_sizes, int n_in,
                              void* d_out, int out_size)
{
    (void)in_sizes; (void)n_in; (void)out_size;
    const float* x     = (const float*)d_in[0];
    const float* wv    = (const float*)d_in[1];
    const float* wq    = (const float*)d_in[2];
    const float* wk    = (const float*)d_in[3];
    const float* gamma = (const float*)d_in[4];
    const float* beta  = (const float*)d_in[5];
    const float* mean  = (const float*)d_in[6];
    const float* var   = (const float*)d_in[7];
    float* out = (float*)d_out;

    cudaFuncSetAttribute(proj_kernel, cudaFuncAttributeMaxDynamicSharedMemorySize, PJ_SZ);
    proj_kernel<<<dim3(64, 5, B_), 256, PJ_SZ>>>(x, wv, wq, wk);
    cudaFuncSetAttribute(attn_kernel, cudaFuncAttributeMaxDynamicSharedMemorySize, SMEM_SZ);
    attn_kernel<<<dim3(128, B_), 256, SMEM_SZ>>>(x, gamma, beta, mean, var, out);
}